// round 2
// baseline (speedup 1.0000x reference)
#include <cuda_runtime.h>
#include <stdint.h>
#include <math.h>

#define Bb 2
#define Tt 8
#define Cc 32
#define HW 4096
#define CHW (Cc*HW)
#define NBT (Bb*Tt)
#define NEL (NBT*CHW)         // 2097152
#define NTOK (NBT*HW)         // 65536

// ---------------- scratch (device globals; no allocation) ----------------
__device__ float g_xnc_r[NEL], g_xnc_i[NEL];
__device__ float g_conv[NBT*64*HW];
__device__ float g_z_r[NEL], g_z_i[NEL];
__device__ float g_znc_r[NEL], g_znc_i[NEL];
__device__ float g_x2_r[NEL], g_x2_i[NEL];
__device__ float g_ctxp[256*32];      // per-block partial |znc| sums (16 bt * 16 sub) * 32 ch
__device__ float g_gain[NBT*Cc];
__device__ float2 g_evo[NBT*Cc];
__device__ float g_h1[(size_t)NTOK*256];

// ---------------- threefry2x32 (JAX partitionable-mode compatible) ----------------
__host__ __device__ __forceinline__ uint32_t tf_rotl(uint32_t x, int r){ return (x<<r)|(x>>(32-r)); }
__host__ __device__ __forceinline__ void tf_block(uint32_t k0,uint32_t k1,uint32_t x0,uint32_t x1,
                                                  uint32_t* o0,uint32_t* o1){
  uint32_t ks2 = k0 ^ k1 ^ 0x1BD11BDAu;
  x0 += k0; x1 += k1;
#define R4(a,b,c,d) x0+=x1; x1=tf_rotl(x1,a); x1^=x0; x0+=x1; x1=tf_rotl(x1,b); x1^=x0; \
                    x0+=x1; x1=tf_rotl(x1,c); x1^=x0; x0+=x1; x1=tf_rotl(x1,d); x1^=x0;
  R4(13,15,26,6)  x0+=k1;  x1+=ks2+1u;
  R4(17,29,16,24) x0+=ks2; x1+=k0+2u;
  R4(13,15,26,6)  x0+=k0;  x1+=k1+3u;
  R4(17,29,16,24) x0+=k1;  x1+=ks2+4u;
  R4(13,15,26,6)  x0+=ks2; x1+=k0+5u;
#undef R4
  *o0=x0; *o1=x1;
}

// partitionable-mode 32-bit random bits for flat index j (< 2^32): hi word = 0
__device__ __forceinline__ float tf_normal(uint32_t k0, uint32_t k1, uint32_t j){
  uint32_t o0,o1;
  tf_block(k0,k1, 0u, j, &o0,&o1);
  uint32_t bits = o0 ^ o1;
  const float lo = -0.99999994f;
  float f = __uint_as_float((bits>>9) | 0x3f800000u) - 1.0f;
  float u = f * (1.0f - lo) + lo;
  u = fmaxf(lo, u);
  return 1.41421356237309515f * erfinvf(u);
}

// ---------------- K1: spatial complex layernorm ----------------
__global__ void k_ln_spatial(const float* __restrict__ xr, const float* __restrict__ xi,
                             const float* __restrict__ lg, const float* __restrict__ lb){
  int idx = blockIdx.x*256 + threadIdx.x;
  int bt = idx >> 12, px = idx & 4095;
  size_t base = (size_t)bt*CHW + px;
  float sum=0.f, ss=0.f;
  #pragma unroll 4
  for (int c=0;c<Cc;c++){
    float r = xr[base + (size_t)c*HW], im = xi[base + (size_t)c*HW];
    sum += r + im; ss += r*r + im*im;
  }
  float mean = sum * (1.0f/64.0f);
  float var  = ss  * (1.0f/64.0f) - mean*mean;
  float inv  = rsqrtf(var + 1e-5f);
  #pragma unroll 4
  for (int c=0;c<Cc;c++){
    float r = xr[base + (size_t)c*HW], im = xi[base + (size_t)c*HW];
    g_xnc_r[base + (size_t)c*HW] = (r - mean)*inv*lg[c]    + lb[c];
    g_xnc_i[base + (size_t)c*HW] = (im - mean)*inv*lg[c+32] + lb[c+32];
  }
}

// ---------------- K2: Clifford 3x3 conv (direct, fp32) ----------------
__global__ void k_conv(const float* __restrict__ cw, const float* __restrict__ cb){
  __shared__ float wsm[64][8][9];
  __shared__ float ts[34][36];
  int tile = blockIdx.x, ocg = blockIdx.y, bt = blockIdx.z;
  int tx0 = (tile & 1)*32, ty0 = (tile >> 1)*32;
  int tid = threadIdx.x, oc0 = ocg*8;
  for (int idx=tid; idx < 8*64*9; idx += 256){
    int ocl = idx/576, rem = idx - ocl*576, ic = rem/9, k = rem - ic*9;
    wsm[ic][ocl][k] = cw[((size_t)(oc0+ocl)*64 + ic)*9 + k];
  }
  float acc[4][8];
  #pragma unroll
  for (int r=0;r<4;r++){ for (int o=0;o<8;o++) acc[r][o]=0.f; }
  int txx = tid & 31, tyy = tid >> 5;
  for (int ic=0; ic<64; ic++){
    const float* plane = (ic < 32 ? g_xnc_r : g_xnc_i) + ((size_t)bt*Cc + (ic & 31))*HW;
    __syncthreads();
    for (int li=tid; li<34*34; li+=256){
      int ly = li/34, lx = li - ly*34;
      int gy = ty0 + ly - 1, gx = tx0 + lx - 1;
      ts[ly][lx] = (gy>=0 && gy<64 && gx>=0 && gx<64) ? plane[gy*64+gx] : 0.f;
    }
    __syncthreads();
    #pragma unroll
    for (int r=0;r<4;r++){
      int yy = tyy + r*8;
      #pragma unroll
      for (int dy=0;dy<3;dy++){
        #pragma unroll
        for (int dx=0;dx<3;dx++){
          float v = ts[yy+dy][txx+dx];
          #pragma unroll
          for (int o=0;o<8;o++) acc[r][o] += v * wsm[ic][o][dy*3+dx];
        }
      }
    }
  }
  #pragma unroll
  for (int r=0;r<4;r++){
    int gy = ty0 + tyy + r*8, gx = tx0 + txx;
    #pragma unroll
    for (int o=0;o<8;o++)
      g_conv[(((size_t)bt*64 + oc0 + o)*64 + gy)*64 + gx] = acc[r][o] + cb[oc0+o];
  }
}

// ---------------- K3: spectral branch (FFT2 -> filter -> IFFT2) + gate combine + residual ----------------
__device__ __forceinline__ float2 cmul(float2 a, float2 b){
  return make_float2(a.x*b.x - a.y*b.y, a.x*b.y + a.y*b.x);
}
__device__ __forceinline__ void fft8(float2 a[8], float sgn){
  const float C1 = 0.70710678118654752440f;
  float2 w1 = make_float2(C1, sgn*C1);
  float2 w2 = make_float2(0.f, sgn);
  float2 w3 = make_float2(-C1, sgn*C1);
  float2 t;
  t = make_float2(a[0].x-a[4].x, a[0].y-a[4].y); a[0].x+=a[4].x; a[0].y+=a[4].y; a[4]=t;
  t = make_float2(a[1].x-a[5].x, a[1].y-a[5].y); a[1].x+=a[5].x; a[1].y+=a[5].y; a[5]=cmul(t,w1);
  t = make_float2(a[2].x-a[6].x, a[2].y-a[6].y); a[2].x+=a[6].x; a[2].y+=a[6].y; a[6]=cmul(t,w2);
  t = make_float2(a[3].x-a[7].x, a[3].y-a[7].y); a[3].x+=a[7].x; a[3].y+=a[7].y; a[7]=cmul(t,w3);
  #pragma unroll
  for (int g=0; g<8; g+=4){
    t = make_float2(a[g].x-a[g+2].x, a[g].y-a[g+2].y); a[g].x+=a[g+2].x; a[g].y+=a[g+2].y; a[g+2]=t;
    t = make_float2(a[g+1].x-a[g+3].x, a[g+1].y-a[g+3].y); a[g+1].x+=a[g+3].x; a[g+1].y+=a[g+3].y; a[g+3]=cmul(t,w2);
  }
  #pragma unroll
  for (int p=0; p<8; p+=2){
    t = make_float2(a[p].x-a[p+1].x, a[p].y-a[p+1].y); a[p].x+=a[p+1].x; a[p].y+=a[p+1].y; a[p+1]=t;
  }
}
__device__ __forceinline__ void fft64_line(float2* p, int st, int b8,
                                           const float2* __restrict__ tw, float sgn, bool conj_tw){
  const int rev[8] = {0,4,2,6,1,5,3,7};
  float2 a[8];
  #pragma unroll
  for (int j=0;j<8;j++) a[j] = p[(8*j + b8)*st];
  fft8(a, sgn);
  #pragma unroll
  for (int c=0;c<8;c++){
    float2 t = tw[(b8*c) & 63];
    if (conj_tw) t.y = -t.y;
    p[(8*c + b8)*st] = cmul(a[rev[c]], t);
  }
  __syncwarp();
  #pragma unroll
  for (int j=0;j<8;j++) a[j] = p[(8*b8 + j)*st];
  fft8(a, sgn);
  __syncwarp();
  #pragma unroll
  for (int d=0;d<8;d++) p[(b8 + 8*d)*st] = a[rev[d]];
  __syncwarp();
}

__global__ void k_spec(const float* __restrict__ swr, const float* __restrict__ swi,
                       const float* __restrict__ gate_p,
                       const float* __restrict__ xr, const float* __restrict__ xi){
  __shared__ float2 sm[64*65];
  __shared__ float2 tw[64];
  int blk = blockIdx.x; int bt = blk >> 5; int c = blk & 31;
  int tid = threadIdx.x;
  if (tid < 64){
    float sv, cv; sincosf(-6.283185307179586f * (float)tid / 64.f, &sv, &cv);
    tw[tid] = make_float2(cv, sv);
  }
  size_t base = ((size_t)bt*Cc + c)*HW;
  for (int i=tid;i<HW;i+=256)
    sm[(i>>6)*65 + (i&63)] = make_float2(g_xnc_r[base+i], g_xnc_i[base+i]);
  __syncthreads();
  int oct = tid >> 3, b8 = tid & 7;
  for (int rep=0; rep<2; rep++) fft64_line(sm + (oct+32*rep)*65, 1, b8, tw, -1.f, false);
  __syncthreads();
  for (int rep=0; rep<2; rep++) fft64_line(sm + (oct+32*rep), 65, b8, tw, -1.f, false);
  __syncthreads();
  size_t coff = (size_t)c*HW;
  for (int i=tid;i<HW;i+=256){
    int h=i>>6, w=i&63;
    sm[h*65+w] = cmul(sm[h*65+w], make_float2(swr[coff+i], swi[coff+i]));
  }
  __syncthreads();
  for (int rep=0; rep<2; rep++) fft64_line(sm + (oct+32*rep)*65, 1, b8, tw, 1.f, true);
  __syncthreads();
  for (int rep=0; rep<2; rep++) fft64_line(sm + (oct+32*rep), 65, b8, tw, 1.f, true);
  __syncthreads();
  float g = gate_p[0];
  const float invN = 1.f/4096.f;
  for (int i=tid;i<HW;i+=256){
    float2 sp = sm[(i>>6)*65 + (i&63)];
    float cr = g_conv[((size_t)bt*64 + c)*HW + i];
    float ci = g_conv[((size_t)bt*64 + 32 + c)*HW + i];
    g_z_r[base+i] = g*cr + (1.f-g)*(sp.x*invN) + xr[base+i];
    g_z_i[base+i] = g*ci + (1.f-g)*(sp.y*invN) + xi[base+i];
  }
}

// ---------------- K4: temporal layernorm + deterministic ctx partials ----------------
__global__ void k_ln_temporal(const float* __restrict__ lg, const float* __restrict__ lb){
  __shared__ float cacc2[8][32];
  int idx = blockIdx.x*256 + threadIdx.x;
  int bt = idx >> 12, px = idx & 4095;
  size_t base = (size_t)bt*CHW + px;
  float sum=0.f, ss=0.f;
  #pragma unroll 4
  for (int c=0;c<Cc;c++){
    float r = g_z_r[base + (size_t)c*HW], im = g_z_i[base + (size_t)c*HW];
    sum += r + im; ss += r*r + im*im;
  }
  float mean = sum * (1.0f/64.0f);
  float var  = ss  * (1.0f/64.0f) - mean*mean;
  float inv  = rsqrtf(var + 1e-5f);
  int lane = threadIdx.x & 31, wid = threadIdx.x >> 5;
  for (int c=0;c<Cc;c++){
    float r = g_z_r[base + (size_t)c*HW], im = g_z_i[base + (size_t)c*HW];
    float nr = (r - mean)*inv*lg[c]    + lb[c];
    float ni = (im - mean)*inv*lg[c+32] + lb[c+32];
    g_znc_r[base + (size_t)c*HW] = nr;
    g_znc_i[base + (size_t)c*HW] = ni;
    float mag = sqrtf(nr*nr + ni*ni);
    #pragma unroll
    for (int off=16; off; off>>=1) mag += __shfl_xor_sync(0xffffffffu, mag, off);
    if (lane == 0) cacc2[wid][c] = mag;
  }
  __syncthreads();
  if (threadIdx.x < 32){
    float s = 0.f;
    #pragma unroll
    for (int w=0; w<8; w++) s += cacc2[w][threadIdx.x];
    g_ctxp[blockIdx.x*32 + threadIdx.x] = s;    // blockIdx = bt*16 + sub
  }
}

// ---------------- K5: evo + input gain (small) ----------------
__global__ void k_gates(const float* __restrict__ dt, const float* __restrict__ alpha,
                        const float* __restrict__ omega, const float* __restrict__ gW,
                        const float* __restrict__ gb){
  int i = threadIdx.x; if (i >= NBT*Cc) return;
  int bt = i >> 5, c = i & 31;
  float dtv = dt[bt];
  float a = alpha[c];
  float sp = (a > 0.f) ? a + log1pf(expf(-a)) : log1pf(expf(a));
  float er = expf(-dtv*sp);
  float sn, cs; sincosf(dtv*omega[c], &sn, &cs);
  g_evo[i] = make_float2(er*cs, er*sn);
  float acc = gb[c];
  for (int k=0;k<32;k++){
    float ctx = 0.f;
    for (int sb=0; sb<16; sb++) ctx += g_ctxp[(bt*16+sb)*32 + k];
    acc += (ctx * (1.f/4096.f)) * gW[k*32 + c];
  }
  g_gain[i] = 1.f/(1.f + expf(-acc));
}

// ---------------- K6: time scan + threefry noise + residual ----------------
__global__ void k_scan(const float* __restrict__ dt, const float* __restrict__ sigma,
                       uint32_t k1a, uint32_t k1b, uint32_t k2a, uint32_t k2b){
  int gid = blockIdx.x*256 + threadIdx.x;
  int b = gid / (Cc*HW); int rem = gid - b*Cc*HW; int c = rem >> 12; int px = rem & 4095;
  float hr=0.f, hi=0.f;
  float sg = sigma[c];
  for (int t=0;t<Tt;t++){
    int btc = (b*Tt + t)*Cc + c;
    size_t base = (size_t)btc*HW + px;
    float2 e = g_evo[btc];
    float gn = g_gain[btc];
    float ur = g_znc_r[base]*gn, ui = g_znc_i[base]*gn;
    float nhr = e.x*hr - e.y*hi + ur;
    float nhi = e.x*hi + e.y*hr + ui;
    hr = nhr; hi = nhi;
    float sc = sg * sqrtf(dt[b*Tt+t] + 1e-6f);
    float er = tf_normal(k1a, k1b, (uint32_t)base);
    float ei = tf_normal(k2a, k2b, (uint32_t)base);
    g_x2_r[base] = hr + sc*er + g_z_r[base];
    g_x2_i[base] = hi + sc*ei + g_z_i[base];
  }
}

// ---------------- K7a: MLP layer 1 (X[65536,64] @ W1[64,256] + b1, GELU) ----------------
__global__ void k_mlp1(const float* __restrict__ w1, const float* __restrict__ b1){
  __shared__ float Xs[64*65];
  __shared__ float Ws[64*65];
  int m0 = blockIdx.x*64, n0 = blockIdx.y*64;
  int tid = threadIdx.x;
  int bt = m0 >> 12, px0 = m0 & 4095;
  for (int idx=tid; idx<4096; idx+=256){
    int m = idx & 63, k = idx >> 6;
    const float* plane = (k < 32) ? g_x2_r : g_x2_i;
    Xs[k*65 + m] = plane[((size_t)bt*Cc + (k & 31))*HW + px0 + m];
  }
  for (int idx=tid; idx<4096; idx+=256){
    int n = idx & 63, k = idx >> 6;
    Ws[k*65 + n] = w1[(size_t)k*256 + n0 + n];
  }
  __syncthreads();
  int tm = tid & 15, tn = tid >> 4;
  float acc[4][4] = {};
  for (int k=0;k<64;k++){
    float xv[4], wv[4];
    #pragma unroll
    for (int i=0;i<4;i++) xv[i] = Xs[k*65 + tm*4 + i];
    #pragma unroll
    for (int j=0;j<4;j++) wv[j] = Ws[k*65 + tn*4 + j];
    #pragma unroll
    for (int i=0;i<4;i++)
      #pragma unroll
      for (int j=0;j<4;j++) acc[i][j] += xv[i]*wv[j];
  }
  #pragma unroll
  for (int i=0;i<4;i++){
    #pragma unroll
    for (int j=0;j<4;j++){
      int m = m0 + tm*4 + i, n = n0 + tn*4 + j;
      float x = acc[i][j] + b1[n];
      float gl = 0.5f*x*(1.f + tanhf(0.7978845608028654f*(x + 0.044715f*x*x*x)));
      g_h1[(size_t)m*256 + n] = gl;
    }
  }
}

// ---------------- K7b: MLP layer 2 (+b2, +x2 residual, write output) ----------------
__global__ void k_mlp2(const float* __restrict__ w2, const float* __restrict__ b2,
                       float* __restrict__ out){
  __shared__ float Hs[64*65];
  __shared__ float Ws[64*65];
  int m0 = blockIdx.x*64;
  int tid = threadIdx.x;
  int tm = tid & 15, tn = tid >> 4;
  float acc[4][4] = {};
  for (int kt=0; kt<4; kt++){
    __syncthreads();
    for (int idx=tid; idx<4096; idx+=256){
      int kk = idx & 63, m = idx >> 6;
      Hs[kk*65 + m] = g_h1[(size_t)(m0+m)*256 + kt*64 + kk];
    }
    for (int idx=tid; idx<4096; idx+=256){
      int n = idx & 63, kk = idx >> 6;
      Ws[kk*65 + n] = w2[(size_t)(kt*64 + kk)*64 + n];
    }
    __syncthreads();
    for (int k=0;k<64;k++){
      float xv[4], wv[4];
      #pragma unroll
      for (int i=0;i<4;i++) xv[i] = Hs[k*65 + tm*4 + i];
      #pragma unroll
      for (int j=0;j<4;j++) wv[j] = Ws[k*65 + tn*4 + j];
      #pragma unroll
      for (int i=0;i<4;i++)
        #pragma unroll
        for (int j=0;j<4;j++) acc[i][j] += xv[i]*wv[j];
    }
  }
  int bt = m0 >> 12, px0 = m0 & 4095;
  #pragma unroll
  for (int i=0;i<4;i++){
    #pragma unroll
    for (int j=0;j<4;j++){
      int m = px0 + tm*4 + i, n = tn*4 + j;
      float res = (n < 32) ? g_x2_r[((size_t)bt*Cc + n)*HW + m]
                           : g_x2_i[((size_t)bt*Cc + (n-32))*HW + m];
      out[((size_t)bt*64 + n)*HW + m] = acc[i][j] + b2[n] + res;
    }
  }
}

// ---------------- host launcher ----------------
extern "C" void kernel_launch(void* const* d_in, const int* in_sizes, int n_in,
                              void* d_out, int out_size){
  const float* x_real = (const float*)d_in[0];
  const float* x_imag = (const float*)d_in[1];
  const float* dt     = (const float*)d_in[2];
  const float* ln_s_g = (const float*)d_in[3];
  const float* ln_s_b = (const float*)d_in[4];
  const float* cliffw = (const float*)d_in[5];
  const float* cliffb = (const float*)d_in[6];
  const float* specwr = (const float*)d_in[7];
  const float* specwi = (const float*)d_in[8];
  const float* gate   = (const float*)d_in[9];
  const float* ln_t_g = (const float*)d_in[10];
  const float* ln_t_b = (const float*)d_in[11];
  const float* alpha  = (const float*)d_in[12];
  const float* omega  = (const float*)d_in[13];
  const float* gain_W = (const float*)d_in[14];
  const float* gain_b = (const float*)d_in[15];
  const float* sigma  = (const float*)d_in[16];
  const float* pw1    = (const float*)d_in[17];
  const float* pb1    = (const float*)d_in[18];
  const float* pw2    = (const float*)d_in[19];
  const float* pb2    = (const float*)d_in[20];
  float* out = (float*)d_out;

  // jax.random.split(jax.random.key(42)) — partitionable (fold-like) mode:
  // keys[i] = threefry_block(key=(0,42), x=(hi=0, lo=i))
  uint32_t k1a,k1b,k2a,k2b;
  tf_block(0u, 42u, 0u, 0u, &k1a, &k1b);   // keys[0]
  tf_block(0u, 42u, 0u, 1u, &k2a, &k2b);   // keys[1]

  k_ln_spatial<<<256, 256>>>(x_real, x_imag, ln_s_g, ln_s_b);
  k_conv<<<dim3(4, 8, 16), 256>>>(cliffw, cliffb);
  k_spec<<<512, 256>>>(specwr, specwi, gate, x_real, x_imag);
  k_ln_temporal<<<256, 256>>>(ln_t_g, ln_t_b);
  k_gates<<<1, 512>>>(dt, alpha, omega, gain_W, gain_b);
  k_scan<<<1024, 256>>>(dt, sigma, k1a, k1b, k2a, k2b);
  k_mlp1<<<dim3(1024, 4), 256>>>(pw1, pb1);
  k_mlp2<<<1024, 256>>>(pw2, pb2, out);
}

// round 3
// speedup vs baseline: 1.1872x; 1.1872x over previous
#include <cuda_runtime.h>
#include <stdint.h>
#include <math.h>

#define Bb 2
#define Tt 8
#define Cc 32
#define HW 4096
#define CHW (Cc*HW)
#define NBT (Bb*Tt)
#define NEL (NBT*CHW)         // 2097152
#define NTOK (NBT*HW)         // 65536

// ---------------- scratch (device globals; no allocation) ----------------
__device__ float g_xnc_r[NEL], g_xnc_i[NEL];
__device__ float g_conv[NBT*64*HW];
__device__ float g_z_r[NEL], g_z_i[NEL];
__device__ float g_znc_r[NEL], g_znc_i[NEL];
__device__ float g_x2_r[NEL], g_x2_i[NEL];
__device__ float g_ctxp[256*32];
__device__ float g_gain[NBT*Cc];
__device__ float2 g_evo[NBT*Cc];
__device__ float g_h1[(size_t)256*NTOK];   // TRANSPOSED: [n][m]

// ---------------- packed f32x2 helpers ----------------
typedef unsigned long long u64t;
__device__ __forceinline__ u64t pk2(float lo, float hi){
  u64t r; asm("mov.b64 %0, {%1, %2};" : "=l"(r) : "f"(lo), "f"(hi)); return r;
}
__device__ __forceinline__ void upk2(u64t v, float& lo, float& hi){
  asm("mov.b64 {%0, %1}, %2;" : "=f"(lo), "=f"(hi) : "l"(v));
}
__device__ __forceinline__ void fma2(u64t& d, u64t a, u64t b){
  asm("fma.rn.f32x2 %0, %1, %2, %3;" : "=l"(d) : "l"(a), "l"(b), "l"(d));
}

// ---------------- threefry2x32 (JAX partitionable-mode compatible) ----------------
__host__ __device__ __forceinline__ uint32_t tf_rotl(uint32_t x, int r){ return (x<<r)|(x>>(32-r)); }
__host__ __device__ __forceinline__ void tf_block(uint32_t k0,uint32_t k1,uint32_t x0,uint32_t x1,
                                                  uint32_t* o0,uint32_t* o1){
  uint32_t ks2 = k0 ^ k1 ^ 0x1BD11BDAu;
  x0 += k0; x1 += k1;
#define R4(a,b,c,d) x0+=x1; x1=tf_rotl(x1,a); x1^=x0; x0+=x1; x1=tf_rotl(x1,b); x1^=x0; \
                    x0+=x1; x1=tf_rotl(x1,c); x1^=x0; x0+=x1; x1=tf_rotl(x1,d); x1^=x0;
  R4(13,15,26,6)  x0+=k1;  x1+=ks2+1u;
  R4(17,29,16,24) x0+=ks2; x1+=k0+2u;
  R4(13,15,26,6)  x0+=k0;  x1+=k1+3u;
  R4(17,29,16,24) x0+=k1;  x1+=ks2+4u;
  R4(13,15,26,6)  x0+=ks2; x1+=k0+5u;
#undef R4
  *o0=x0; *o1=x1;
}

__device__ __forceinline__ float tf_normal(uint32_t k0, uint32_t k1, uint32_t j){
  uint32_t o0,o1;
  tf_block(k0,k1, 0u, j, &o0,&o1);
  uint32_t bits = o0 ^ o1;
  const float lo = -0.99999994f;
  float f = __uint_as_float((bits>>9) | 0x3f800000u) - 1.0f;
  float u = f * (1.0f - lo) + lo;
  u = fmaxf(lo, u);
  return 1.41421356237309515f * erfinvf(u);
}

// ---------------- K1: spatial complex layernorm ----------------
__global__ void k_ln_spatial(const float* __restrict__ xr, const float* __restrict__ xi,
                             const float* __restrict__ lg, const float* __restrict__ lb){
  int idx = blockIdx.x*256 + threadIdx.x;
  int bt = idx >> 12, px = idx & 4095;
  size_t base = (size_t)bt*CHW + px;
  float sum=0.f, ss=0.f;
  #pragma unroll 4
  for (int c=0;c<Cc;c++){
    float r = xr[base + (size_t)c*HW], im = xi[base + (size_t)c*HW];
    sum += r + im; ss += r*r + im*im;
  }
  float mean = sum * (1.0f/64.0f);
  float var  = ss  * (1.0f/64.0f) - mean*mean;
  float inv  = rsqrtf(var + 1e-5f);
  #pragma unroll 4
  for (int c=0;c<Cc;c++){
    float r = xr[base + (size_t)c*HW], im = xi[base + (size_t)c*HW];
    g_xnc_r[base + (size_t)c*HW] = (r - mean)*inv*lg[c]    + lb[c];
    g_xnc_i[base + (size_t)c*HW] = (im - mean)*inv*lg[c+32] + lb[c+32];
  }
}

// ---------------- K2: Clifford 3x3 conv (f32x2 packed over oc pairs) ----------------
__global__ void k_conv(const float* __restrict__ cw, const float* __restrict__ cb){
  __shared__ float2 wsm2[64][4][9];    // [ic][opair][k] -> (oc0+2op, oc0+2op+1)
  __shared__ float ts[34][36];
  int tile = blockIdx.x, ocg = blockIdx.y, bt = blockIdx.z;
  int tx0 = (tile & 1)*32, ty0 = (tile >> 1)*32;
  int tid = threadIdx.x, oc0 = ocg*8;
  for (int idx=tid; idx < 64*4*9; idx += 256){
    int ic = idx/36, rem = idx - ic*36, op = rem/9, k = rem - op*9;
    int oc = oc0 + 2*op;
    wsm2[ic][op][k] = make_float2(cw[((size_t)oc*64 + ic)*9 + k],
                                  cw[((size_t)(oc+1)*64 + ic)*9 + k]);
  }
  u64t acc2[4][4];
  #pragma unroll
  for (int r=0;r<4;r++)
    #pragma unroll
    for (int op=0;op<4;op++) acc2[r][op] = 0ull;
  int txx = tid & 31, tyy = tid >> 5;
  for (int ic=0; ic<64; ic++){
    const float* plane = (ic < 32 ? g_xnc_r : g_xnc_i) + ((size_t)bt*Cc + (ic & 31))*HW;
    __syncthreads();
    for (int li=tid; li<34*34; li+=256){
      int ly = li/34, lx = li - ly*34;
      int gy = ty0 + ly - 1, gx = tx0 + lx - 1;
      ts[ly][lx] = (gy>=0 && gy<64 && gx>=0 && gx<64) ? plane[gy*64+gx] : 0.f;
    }
    __syncthreads();
    #pragma unroll
    for (int r=0;r<4;r++){
      int yy = tyy + r*8;
      #pragma unroll
      for (int dy=0;dy<3;dy++){
        #pragma unroll
        for (int dx=0;dx<3;dx++){
          float v = ts[yy+dy][txx+dx];
          u64t vv = pk2(v, v);
          #pragma unroll
          for (int op=0;op<4;op++)
            fma2(acc2[r][op], vv, *(const u64t*)&wsm2[ic][op][dy*3+dx]);
        }
      }
    }
  }
  #pragma unroll
  for (int r=0;r<4;r++){
    int gy = ty0 + tyy + r*8, gx = tx0 + txx;
    #pragma unroll
    for (int op=0;op<4;op++){
      float a0, a1; upk2(acc2[r][op], a0, a1);
      int oc = oc0 + 2*op;
      g_conv[(((size_t)bt*64 + oc  )*64 + gy)*64 + gx] = a0 + cb[oc];
      g_conv[(((size_t)bt*64 + oc+1)*64 + gy)*64 + gx] = a1 + cb[oc+1];
    }
  }
}

// ---------------- K3: spectral branch (FFT2 -> filter -> IFFT2) + gate combine + residual ----------------
__device__ __forceinline__ float2 cmul(float2 a, float2 b){
  return make_float2(a.x*b.x - a.y*b.y, a.x*b.y + a.y*b.x);
}
__device__ __forceinline__ void fft8(float2 a[8], float sgn){
  const float C1 = 0.70710678118654752440f;
  float2 w1 = make_float2(C1, sgn*C1);
  float2 w2 = make_float2(0.f, sgn);
  float2 w3 = make_float2(-C1, sgn*C1);
  float2 t;
  t = make_float2(a[0].x-a[4].x, a[0].y-a[4].y); a[0].x+=a[4].x; a[0].y+=a[4].y; a[4]=t;
  t = make_float2(a[1].x-a[5].x, a[1].y-a[5].y); a[1].x+=a[5].x; a[1].y+=a[5].y; a[5]=cmul(t,w1);
  t = make_float2(a[2].x-a[6].x, a[2].y-a[6].y); a[2].x+=a[6].x; a[2].y+=a[6].y; a[6]=cmul(t,w2);
  t = make_float2(a[3].x-a[7].x, a[3].y-a[7].y); a[3].x+=a[7].x; a[3].y+=a[7].y; a[7]=cmul(t,w3);
  #pragma unroll
  for (int g=0; g<8; g+=4){
    t = make_float2(a[g].x-a[g+2].x, a[g].y-a[g+2].y); a[g].x+=a[g+2].x; a[g].y+=a[g+2].y; a[g+2]=t;
    t = make_float2(a[g+1].x-a[g+3].x, a[g+1].y-a[g+3].y); a[g+1].x+=a[g+3].x; a[g+1].y+=a[g+3].y; a[g+3]=cmul(t,w2);
  }
  #pragma unroll
  for (int p=0; p<8; p+=2){
    t = make_float2(a[p].x-a[p+1].x, a[p].y-a[p+1].y); a[p].x+=a[p+1].x; a[p].y+=a[p+1].y; a[p+1]=t;
  }
}
__device__ __forceinline__ void fft64_line(float2* p, int st, int b8,
                                           const float2* __restrict__ tw, float sgn, bool conj_tw){
  const int rev[8] = {0,4,2,6,1,5,3,7};
  float2 a[8];
  #pragma unroll
  for (int j=0;j<8;j++) a[j] = p[(8*j + b8)*st];
  fft8(a, sgn);
  #pragma unroll
  for (int c=0;c<8;c++){
    float2 t = tw[(b8*c) & 63];
    if (conj_tw) t.y = -t.y;
    p[(8*c + b8)*st] = cmul(a[rev[c]], t);
  }
  __syncwarp();
  #pragma unroll
  for (int j=0;j<8;j++) a[j] = p[(8*b8 + j)*st];
  fft8(a, sgn);
  __syncwarp();
  #pragma unroll
  for (int d=0;d<8;d++) p[(b8 + 8*d)*st] = a[rev[d]];
  __syncwarp();
}

__global__ void k_spec(const float* __restrict__ swr, const float* __restrict__ swi,
                       const float* __restrict__ gate_p,
                       const float* __restrict__ xr, const float* __restrict__ xi){
  __shared__ float2 sm[64*65];
  __shared__ float2 tw[64];
  int blk = blockIdx.x; int bt = blk >> 5; int c = blk & 31;
  int tid = threadIdx.x;
  if (tid < 64){
    float sv, cv; sincosf(-6.283185307179586f * (float)tid / 64.f, &sv, &cv);
    tw[tid] = make_float2(cv, sv);
  }
  size_t base = ((size_t)bt*Cc + c)*HW;
  for (int i=tid;i<HW;i+=256)
    sm[(i>>6)*65 + (i&63)] = make_float2(g_xnc_r[base+i], g_xnc_i[base+i]);
  __syncthreads();
  int oct = tid >> 3, b8 = tid & 7;
  for (int rep=0; rep<2; rep++) fft64_line(sm + (oct+32*rep)*65, 1, b8, tw, -1.f, false);
  __syncthreads();
  for (int rep=0; rep<2; rep++) fft64_line(sm + (oct+32*rep), 65, b8, tw, -1.f, false);
  __syncthreads();
  size_t coff = (size_t)c*HW;
  for (int i=tid;i<HW;i+=256){
    int h=i>>6, w=i&63;
    sm[h*65+w] = cmul(sm[h*65+w], make_float2(swr[coff+i], swi[coff+i]));
  }
  __syncthreads();
  for (int rep=0; rep<2; rep++) fft64_line(sm + (oct+32*rep)*65, 1, b8, tw, 1.f, true);
  __syncthreads();
  for (int rep=0; rep<2; rep++) fft64_line(sm + (oct+32*rep), 65, b8, tw, 1.f, true);
  __syncthreads();
  float g = gate_p[0];
  const float invN = 1.f/4096.f;
  for (int i=tid;i<HW;i+=256){
    float2 sp = sm[(i>>6)*65 + (i&63)];
    float cr = g_conv[((size_t)bt*64 + c)*HW + i];
    float ci = g_conv[((size_t)bt*64 + 32 + c)*HW + i];
    g_z_r[base+i] = g*cr + (1.f-g)*(sp.x*invN) + xr[base+i];
    g_z_i[base+i] = g*ci + (1.f-g)*(sp.y*invN) + xi[base+i];
  }
}

// ---------------- K4: temporal layernorm + deterministic ctx partials ----------------
__global__ void k_ln_temporal(const float* __restrict__ lg, const float* __restrict__ lb){
  __shared__ float cacc2[8][32];
  int idx = blockIdx.x*256 + threadIdx.x;
  int bt = idx >> 12, px = idx & 4095;
  size_t base = (size_t)bt*CHW + px;
  float sum=0.f, ss=0.f;
  #pragma unroll 4
  for (int c=0;c<Cc;c++){
    float r = g_z_r[base + (size_t)c*HW], im = g_z_i[base + (size_t)c*HW];
    sum += r + im; ss += r*r + im*im;
  }
  float mean = sum * (1.0f/64.0f);
  float var  = ss  * (1.0f/64.0f) - mean*mean;
  float inv  = rsqrtf(var + 1e-5f);
  int lane = threadIdx.x & 31, wid = threadIdx.x >> 5;
  for (int c=0;c<Cc;c++){
    float r = g_z_r[base + (size_t)c*HW], im = g_z_i[base + (size_t)c*HW];
    float nr = (r - mean)*inv*lg[c]    + lb[c];
    float ni = (im - mean)*inv*lg[c+32] + lb[c+32];
    g_znc_r[base + (size_t)c*HW] = nr;
    g_znc_i[base + (size_t)c*HW] = ni;
    float mag = sqrtf(nr*nr + ni*ni);
    #pragma unroll
    for (int off=16; off; off>>=1) mag += __shfl_xor_sync(0xffffffffu, mag, off);
    if (lane == 0) cacc2[wid][c] = mag;
  }
  __syncthreads();
  if (threadIdx.x < 32){
    float s = 0.f;
    #pragma unroll
    for (int w=0; w<8; w++) s += cacc2[w][threadIdx.x];
    g_ctxp[blockIdx.x*32 + threadIdx.x] = s;
  }
}

// ---------------- K5: evo + input gain (small) ----------------
__global__ void k_gates(const float* __restrict__ dt, const float* __restrict__ alpha,
                        const float* __restrict__ omega, const float* __restrict__ gW,
                        const float* __restrict__ gb){
  int i = threadIdx.x; if (i >= NBT*Cc) return;
  int bt = i >> 5, c = i & 31;
  float dtv = dt[bt];
  float a = alpha[c];
  float sp = (a > 0.f) ? a + log1pf(expf(-a)) : log1pf(expf(a));
  float er = expf(-dtv*sp);
  float sn, cs; sincosf(dtv*omega[c], &sn, &cs);
  g_evo[i] = make_float2(er*cs, er*sn);
  float acc = gb[c];
  for (int k=0;k<32;k++){
    float ctx = 0.f;
    for (int sb=0; sb<16; sb++) ctx += g_ctxp[(bt*16+sb)*32 + k];
    acc += (ctx * (1.f/4096.f)) * gW[k*32 + c];
  }
  g_gain[i] = 1.f/(1.f + expf(-acc));
}

// ---------------- K6: time scan + threefry noise + residual ----------------
__global__ void k_scan(const float* __restrict__ dt, const float* __restrict__ sigma,
                       uint32_t k1a, uint32_t k1b, uint32_t k2a, uint32_t k2b){
  int gid = blockIdx.x*256 + threadIdx.x;
  int b = gid / (Cc*HW); int rem = gid - b*Cc*HW; int c = rem >> 12; int px = rem & 4095;
  float hr=0.f, hi=0.f;
  float sg = sigma[c];
  for (int t=0;t<Tt;t++){
    int btc = (b*Tt + t)*Cc + c;
    size_t base = (size_t)btc*HW + px;
    float2 e = g_evo[btc];
    float gn = g_gain[btc];
    float ur = g_znc_r[base]*gn, ui = g_znc_i[base]*gn;
    float nhr = e.x*hr - e.y*hi + ur;
    float nhi = e.x*hi + e.y*hr + ui;
    hr = nhr; hi = nhi;
    float sc = sg * sqrtf(dt[b*Tt+t] + 1e-6f);
    float er = tf_normal(k1a, k1b, (uint32_t)base);
    float ei = tf_normal(k2a, k2b, (uint32_t)base);
    g_x2_r[base] = hr + sc*er + g_z_r[base];
    g_x2_i[base] = hi + sc*ei + g_z_i[base];
  }
}

// ---------------- K7a: MLP layer 1 (f32x2, 128x64 tile, h1 stored transposed [n][m]) ----------------
__global__ void k_mlp1(const float* __restrict__ w1, const float* __restrict__ b1){
  __shared__ float Xs[64*128];   // [k][m]
  __shared__ float Ws[64*64];    // [k][n]
  int m0 = blockIdx.x*128, n0 = blockIdx.y*64;
  int tid = threadIdx.x;
  int bt = m0 >> 12, px0 = m0 & 4095;
  for (int idx=tid; idx<64*128; idx+=256){
    int m = idx & 127, k = idx >> 7;
    const float* plane = (k < 32) ? g_x2_r : g_x2_i;
    Xs[k*128 + m] = plane[((size_t)bt*Cc + (k & 31))*HW + px0 + m];
  }
  for (int idx=tid; idx<64*64; idx+=256){
    int n = idx & 63, k = idx >> 6;
    Ws[k*64 + n] = w1[(size_t)k*256 + n0 + n];
  }
  __syncthreads();
  int tm = tid & 15, tn = tid >> 4;   // 16 m-groups (8 m each, stride 16), 16 n-groups (4 n each)
  u64t acc2[8][2];
  #pragma unroll
  for (int i=0;i<8;i++){ acc2[i][0]=0ull; acc2[i][1]=0ull; }
  for (int k=0;k<64;k++){
    u64t w0 = *(const u64t*)&Ws[k*64 + tn*4];
    u64t w1v = *(const u64t*)&Ws[k*64 + tn*4 + 2];
    #pragma unroll
    for (int ii=0;ii<8;ii++){
      float x = Xs[k*128 + tm + 16*ii];
      u64t xx = pk2(x, x);
      fma2(acc2[ii][0], xx, w0);
      fma2(acc2[ii][1], xx, w1v);
    }
  }
  #pragma unroll
  for (int ii=0;ii<8;ii++){
    int m = m0 + tm + 16*ii;
    #pragma unroll
    for (int jp=0;jp<2;jp++){
      float a0, a1; upk2(acc2[ii][jp], a0, a1);
      #pragma unroll
      for (int l=0;l<2;l++){
        int n = n0 + tn*4 + 2*jp + l;
        float x = (l==0 ? a0 : a1) + b1[n];
        float gl = 0.5f*x*(1.f + tanhf(0.7978845608028654f*(x + 0.044715f*x*x*x)));
        g_h1[(size_t)n*NTOK + m] = gl;
      }
    }
  }
}

// ---------------- K7b: MLP layer 2 (f32x2, +b2, +x2 residual, write output) ----------------
__global__ void k_mlp2(const float* __restrict__ w2, const float* __restrict__ b2,
                       float* __restrict__ out){
  __shared__ float Hs[64*128];   // [kk][m]
  __shared__ float Ws[64*64];    // [kk][n]
  int m0 = blockIdx.x*128;
  int tid = threadIdx.x;
  int tm = tid & 15, tn = tid >> 4;
  u64t acc2[8][2];
  #pragma unroll
  for (int i=0;i<8;i++){ acc2[i][0]=0ull; acc2[i][1]=0ull; }
  for (int kt=0; kt<4; kt++){
    __syncthreads();
    for (int idx=tid; idx<64*128; idx+=256){
      int m = idx & 127, kk = idx >> 7;
      Hs[kk*128 + m] = g_h1[(size_t)(kt*64 + kk)*NTOK + m0 + m];
    }
    for (int idx=tid; idx<64*64; idx+=256){
      int n = idx & 63, kk = idx >> 6;
      Ws[kk*64 + n] = w2[(size_t)(kt*64 + kk)*64 + n];
    }
    __syncthreads();
    for (int k=0;k<64;k++){
      u64t w0 = *(const u64t*)&Ws[k*64 + tn*4];
      u64t w1v = *(const u64t*)&Ws[k*64 + tn*4 + 2];
      #pragma unroll
      for (int ii=0;ii<8;ii++){
        float x = Hs[k*128 + tm + 16*ii];
        u64t xx = pk2(x, x);
        fma2(acc2[ii][0], xx, w0);
        fma2(acc2[ii][1], xx, w1v);
      }
    }
  }
  int bt = m0 >> 12, px0 = m0 & 4095;
  #pragma unroll
  for (int ii=0;ii<8;ii++){
    int m = px0 + tm + 16*ii;
    #pragma unroll
    for (int jp=0;jp<2;jp++){
      float a0, a1; upk2(acc2[ii][jp], a0, a1);
      #pragma unroll
      for (int l=0;l<2;l++){
        int n = tn*4 + 2*jp + l;
        float v = (l==0 ? a0 : a1) + b2[n];
        float res = (n < 32) ? g_x2_r[((size_t)bt*Cc + n)*HW + m]
                             : g_x2_i[((size_t)bt*Cc + (n-32))*HW + m];
        out[((size_t)bt*64 + n)*HW + m] = v + res;
      }
    }
  }
}

// ---------------- host launcher ----------------
extern "C" void kernel_launch(void* const* d_in, const int* in_sizes, int n_in,
                              void* d_out, int out_size){
  const float* x_real = (const float*)d_in[0];
  const float* x_imag = (const float*)d_in[1];
  const float* dt     = (const float*)d_in[2];
  const float* ln_s_g = (const float*)d_in[3];
  const float* ln_s_b = (const float*)d_in[4];
  const float* cliffw = (const float*)d_in[5];
  const float* cliffb = (const float*)d_in[6];
  const float* specwr = (const float*)d_in[7];
  const float* specwi = (const float*)d_in[8];
  const float* gate   = (const float*)d_in[9];
  const float* ln_t_g = (const float*)d_in[10];
  const float* ln_t_b = (const float*)d_in[11];
  const float* alpha  = (const float*)d_in[12];
  const float* omega  = (const float*)d_in[13];
  const float* gain_W = (const float*)d_in[14];
  const float* gain_b = (const float*)d_in[15];
  const float* sigma  = (const float*)d_in[16];
  const float* pw1    = (const float*)d_in[17];
  const float* pb1    = (const float*)d_in[18];
  const float* pw2    = (const float*)d_in[19];
  const float* pb2    = (const float*)d_in[20];
  float* out = (float*)d_out;

  uint32_t k1a,k1b,k2a,k2b;
  tf_block(0u, 42u, 0u, 0u, &k1a, &k1b);   // keys[0]
  tf_block(0u, 42u, 0u, 1u, &k2a, &k2b);   // keys[1]

  k_ln_spatial<<<256, 256>>>(x_real, x_imag, ln_s_g, ln_s_b);
  k_conv<<<dim3(4, 8, 16), 256>>>(cliffw, cliffb);
  k_spec<<<512, 256>>>(specwr, specwi, gate, x_real, x_imag);
  k_ln_temporal<<<256, 256>>>(ln_t_g, ln_t_b);
  k_gates<<<1, 512>>>(dt, alpha, omega, gain_W, gain_b);
  k_scan<<<1024, 256>>>(dt, sigma, k1a, k1b, k2a, k2b);
  k_mlp1<<<dim3(512, 4), 256>>>(pw1, pb1);
  k_mlp2<<<512, 256>>>(pw2, pb2, out);
}

// round 4
// speedup vs baseline: 1.4224x; 1.1981x over previous
#include <cuda_runtime.h>
#include <stdint.h>
#include <math.h>

#define Bb 2
#define Tt 8
#define Cc 32
#define HW 4096
#define CHW (Cc*HW)
#define NBT (Bb*Tt)
#define NEL (NBT*CHW)         // 2097152
#define NTOK (NBT*HW)         // 65536

// ---------------- scratch (device globals; no allocation) ----------------
__device__ float g_xnc_r[NEL], g_xnc_i[NEL];
__device__ float g_conv[NBT*64*HW];
__device__ float g_z_r[NEL], g_z_i[NEL];
__device__ float g_znc_r[NEL], g_znc_i[NEL];
__device__ float g_x2_r[NEL], g_x2_i[NEL];
__device__ float g_ctxp[128*32];      // 128 blocks (16 bt * 8 sub) * 32 ch
__device__ float g_gain[NBT*Cc];
__device__ float2 g_evo[NBT*Cc];

// ---------------- packed f32x2 helpers ----------------
typedef unsigned long long u64t;
__device__ __forceinline__ u64t pk2(float lo, float hi){
  u64t r; asm("mov.b64 %0, {%1, %2};" : "=l"(r) : "f"(lo), "f"(hi)); return r;
}
__device__ __forceinline__ void upk2(u64t v, float& lo, float& hi){
  asm("mov.b64 {%0, %1}, %2;" : "=f"(lo), "=f"(hi) : "l"(v));
}
__device__ __forceinline__ void fma2(u64t& d, u64t a, u64t b){
  asm("fma.rn.f32x2 %0, %1, %2, %3;" : "=l"(d) : "l"(a), "l"(b), "l"(d));
}

// ---------------- threefry2x32 (JAX partitionable-mode compatible) ----------------
__host__ __device__ __forceinline__ uint32_t tf_rotl(uint32_t x, int r){ return (x<<r)|(x>>(32-r)); }
__host__ __device__ __forceinline__ void tf_block(uint32_t k0,uint32_t k1,uint32_t x0,uint32_t x1,
                                                  uint32_t* o0,uint32_t* o1){
  uint32_t ks2 = k0 ^ k1 ^ 0x1BD11BDAu;
  x0 += k0; x1 += k1;
#define R4(a,b,c,d) x0+=x1; x1=tf_rotl(x1,a); x1^=x0; x0+=x1; x1=tf_rotl(x1,b); x1^=x0; \
                    x0+=x1; x1=tf_rotl(x1,c); x1^=x0; x0+=x1; x1=tf_rotl(x1,d); x1^=x0;
  R4(13,15,26,6)  x0+=k1;  x1+=ks2+1u;
  R4(17,29,16,24) x0+=ks2; x1+=k0+2u;
  R4(13,15,26,6)  x0+=k0;  x1+=k1+3u;
  R4(17,29,16,24) x0+=k1;  x1+=ks2+4u;
  R4(13,15,26,6)  x0+=ks2; x1+=k0+5u;
#undef R4
  *o0=x0; *o1=x1;
}

__device__ __forceinline__ float tf_normal(uint32_t k0, uint32_t k1, uint32_t j){
  uint32_t o0,o1;
  tf_block(k0,k1, 0u, j, &o0,&o1);
  uint32_t bits = o0 ^ o1;
  const float lo = -0.99999994f;
  float f = __uint_as_float((bits>>9) | 0x3f800000u) - 1.0f;
  float u = f * (1.0f - lo) + lo;
  u = fmaxf(lo, u);
  return 1.41421356237309515f * erfinvf(u);
}

// ---------------- K1: spatial complex layernorm (2 px / thread) ----------------
__global__ void k_ln_spatial(const float* __restrict__ xr, const float* __restrict__ xi,
                             const float* __restrict__ lg, const float* __restrict__ lb){
  int idx = blockIdx.x*256 + threadIdx.x;     // 32768 threads, each 2 px
  int bt = idx >> 11, p2 = idx & 2047;
  size_t base = (size_t)bt*CHW + p2*2;
  float s0=0.f,s1=0.f,q0=0.f,q1=0.f;
  #pragma unroll 8
  for (int c=0;c<Cc;c++){
    float2 r = *(const float2*)&xr[base + (size_t)c*HW];
    float2 im = *(const float2*)&xi[base + (size_t)c*HW];
    s0 += r.x + im.x; s1 += r.y + im.y;
    q0 += r.x*r.x + im.x*im.x; q1 += r.y*r.y + im.y*im.y;
  }
  float m0 = s0*(1.f/64.f), m1 = s1*(1.f/64.f);
  float i0 = rsqrtf(q0*(1.f/64.f) - m0*m0 + 1e-5f);
  float i1 = rsqrtf(q1*(1.f/64.f) - m1*m1 + 1e-5f);
  #pragma unroll 8
  for (int c=0;c<Cc;c++){
    float2 r = *(const float2*)&xr[base + (size_t)c*HW];
    float2 im = *(const float2*)&xi[base + (size_t)c*HW];
    float gr = lg[c], br = lb[c], gi = lg[c+32], bi = lb[c+32];
    *(float2*)&g_xnc_r[base + (size_t)c*HW] = make_float2((r.x-m0)*i0*gr+br, (r.y-m1)*i1*gr+br);
    *(float2*)&g_xnc_i[base + (size_t)c*HW] = make_float2((im.x-m0)*i0*gi+bi, (im.y-m1)*i1*gi+bi);
  }
}

// ---------------- K2: Clifford 3x3 conv (4 consecutive rows/thread, f32x2 oc-pairs) ----------------
__global__ void k_conv(const float* __restrict__ cw, const float* __restrict__ cb){
  __shared__ float2 wsm2[64][9][4];    // [ic][tap][opair]
  __shared__ float ts[34][36];
  int tile = blockIdx.x, ocg = blockIdx.y, bt = blockIdx.z;
  int tx0 = (tile & 1)*32, ty0 = (tile >> 1)*32;
  int tid = threadIdx.x, oc0 = ocg*8;
  for (int idx=tid; idx < 64*9*4; idx += 256){
    int op = idx & 3, tap = (idx>>2)%9, ic = idx/36;
    int oc = oc0 + 2*op;
    wsm2[ic][tap][op] = make_float2(cw[((size_t)oc*64 + ic)*9 + tap],
                                    cw[((size_t)(oc+1)*64 + ic)*9 + tap]);
  }
  u64t acc2[4][4];   // [q row][opair]
  #pragma unroll
  for (int q=0;q<4;q++)
    #pragma unroll
    for (int op=0;op<4;op++) acc2[q][op] = 0ull;
  int txx = tid & 31, tyy = tid >> 5;   // col, rowgroup (4 consecutive rows)
  for (int ic=0; ic<64; ic++){
    const float* plane = (ic < 32 ? g_xnc_r : g_xnc_i) + ((size_t)bt*Cc + (ic & 31))*HW;
    __syncthreads();
    for (int li=tid; li<34*34; li+=256){
      int ly = li/34, lx = li - ly*34;
      int gy = ty0 + ly - 1, gx = tx0 + lx - 1;
      ts[ly][lx] = (gy>=0 && gy<64 && gx>=0 && gx<64) ? plane[gy*64+gx] : 0.f;
    }
    __syncthreads();
    // stage 6x3 window into packed regs
    u64t tsp[6][3];
    #pragma unroll
    for (int s=0;s<6;s++)
      #pragma unroll
      for (int d=0;d<3;d++){
        float v = ts[tyy*4 + s][txx + d];
        tsp[s][d] = pk2(v, v);
      }
    #pragma unroll
    for (int dy=0;dy<3;dy++){
      #pragma unroll
      for (int dx=0;dx<3;dx++){
        const u64t* wp = (const u64t*)&wsm2[ic][dy*3+dx][0];
        u64t w0 = wp[0], w1 = wp[1], w2 = wp[2], w3 = wp[3];
        #pragma unroll
        for (int q=0;q<4;q++){
          fma2(acc2[q][0], tsp[q+dy][dx], w0);
          fma2(acc2[q][1], tsp[q+dy][dx], w1);
          fma2(acc2[q][2], tsp[q+dy][dx], w2);
          fma2(acc2[q][3], tsp[q+dy][dx], w3);
        }
      }
    }
  }
  #pragma unroll
  for (int q=0;q<4;q++){
    int gy = ty0 + tyy*4 + q, gx = tx0 + txx;
    #pragma unroll
    for (int op=0;op<4;op++){
      float a0, a1; upk2(acc2[q][op], a0, a1);
      int oc = oc0 + 2*op;
      g_conv[(((size_t)bt*64 + oc  )*64 + gy)*64 + gx] = a0 + cb[oc];
      g_conv[(((size_t)bt*64 + oc+1)*64 + gy)*64 + gx] = a1 + cb[oc+1];
    }
  }
}

// ---------------- K3: spectral branch ----------------
__device__ __forceinline__ float2 cmul(float2 a, float2 b){
  return make_float2(a.x*b.x - a.y*b.y, a.x*b.y + a.y*b.x);
}
__device__ __forceinline__ void fft8(float2 a[8], float sgn){
  const float C1 = 0.70710678118654752440f;
  float2 w1 = make_float2(C1, sgn*C1);
  float2 w2 = make_float2(0.f, sgn);
  float2 w3 = make_float2(-C1, sgn*C1);
  float2 t;
  t = make_float2(a[0].x-a[4].x, a[0].y-a[4].y); a[0].x+=a[4].x; a[0].y+=a[4].y; a[4]=t;
  t = make_float2(a[1].x-a[5].x, a[1].y-a[5].y); a[1].x+=a[5].x; a[1].y+=a[5].y; a[5]=cmul(t,w1);
  t = make_float2(a[2].x-a[6].x, a[2].y-a[6].y); a[2].x+=a[6].x; a[2].y+=a[6].y; a[6]=cmul(t,w2);
  t = make_float2(a[3].x-a[7].x, a[3].y-a[7].y); a[3].x+=a[7].x; a[3].y+=a[7].y; a[7]=cmul(t,w3);
  #pragma unroll
  for (int g=0; g<8; g+=4){
    t = make_float2(a[g].x-a[g+2].x, a[g].y-a[g+2].y); a[g].x+=a[g+2].x; a[g].y+=a[g+2].y; a[g+2]=t;
    t = make_float2(a[g+1].x-a[g+3].x, a[g+1].y-a[g+3].y); a[g+1].x+=a[g+3].x; a[g+1].y+=a[g+3].y; a[g+3]=cmul(t,w2);
  }
  #pragma unroll
  for (int p=0; p<8; p+=2){
    t = make_float2(a[p].x-a[p+1].x, a[p].y-a[p+1].y); a[p].x+=a[p+1].x; a[p].y+=a[p+1].y; a[p+1]=t;
  }
}
__device__ __forceinline__ void fft64_line(float2* p, int st, int b8,
                                           const float2* __restrict__ tw, float sgn, bool conj_tw){
  const int rev[8] = {0,4,2,6,1,5,3,7};
  float2 a[8];
  #pragma unroll
  for (int j=0;j<8;j++) a[j] = p[(8*j + b8)*st];
  fft8(a, sgn);
  #pragma unroll
  for (int c=0;c<8;c++){
    float2 t = tw[(b8*c) & 63];
    if (conj_tw) t.y = -t.y;
    p[(8*c + b8)*st] = cmul(a[rev[c]], t);
  }
  __syncwarp();
  #pragma unroll
  for (int j=0;j<8;j++) a[j] = p[(8*b8 + j)*st];
  fft8(a, sgn);
  __syncwarp();
  #pragma unroll
  for (int d=0;d<8;d++) p[(b8 + 8*d)*st] = a[rev[d]];
  __syncwarp();
}

__global__ void k_spec(const float* __restrict__ swr, const float* __restrict__ swi,
                       const float* __restrict__ gate_p,
                       const float* __restrict__ xr, const float* __restrict__ xi){
  __shared__ float2 sm[64*65];
  __shared__ float2 tw[64];
  int blk = blockIdx.x; int bt = blk >> 5; int c = blk & 31;
  int tid = threadIdx.x;
  if (tid < 64){
    float sv, cv; sincosf(-6.283185307179586f * (float)tid / 64.f, &sv, &cv);
    tw[tid] = make_float2(cv, sv);
  }
  size_t base = ((size_t)bt*Cc + c)*HW;
  for (int i=tid;i<HW;i+=256)
    sm[(i>>6)*65 + (i&63)] = make_float2(g_xnc_r[base+i], g_xnc_i[base+i]);
  __syncthreads();
  int oct = tid >> 3, b8 = tid & 7;
  for (int rep=0; rep<2; rep++) fft64_line(sm + (oct+32*rep)*65, 1, b8, tw, -1.f, false);
  __syncthreads();
  for (int rep=0; rep<2; rep++) fft64_line(sm + (oct+32*rep), 65, b8, tw, -1.f, false);
  __syncthreads();
  size_t coff = (size_t)c*HW;
  for (int i=tid;i<HW;i+=256){
    int h=i>>6, w=i&63;
    sm[h*65+w] = cmul(sm[h*65+w], make_float2(swr[coff+i], swi[coff+i]));
  }
  __syncthreads();
  for (int rep=0; rep<2; rep++) fft64_line(sm + (oct+32*rep)*65, 1, b8, tw, 1.f, true);
  __syncthreads();
  for (int rep=0; rep<2; rep++) fft64_line(sm + (oct+32*rep), 65, b8, tw, 1.f, true);
  __syncthreads();
  float g = gate_p[0];
  const float invN = 1.f/4096.f;
  for (int i=tid;i<HW;i+=256){
    float2 sp = sm[(i>>6)*65 + (i&63)];
    float cr = g_conv[((size_t)bt*64 + c)*HW + i];
    float ci = g_conv[((size_t)bt*64 + 32 + c)*HW + i];
    g_z_r[base+i] = g*cr + (1.f-g)*(sp.x*invN) + xr[base+i];
    g_z_i[base+i] = g*ci + (1.f-g)*(sp.y*invN) + xi[base+i];
  }
}

// ---------------- K4: temporal layernorm + ctx partials (2 px / thread) ----------------
__global__ void k_ln_temporal(const float* __restrict__ lg, const float* __restrict__ lb){
  __shared__ float cacc2[8][32];
  int idx = blockIdx.x*256 + threadIdx.x;     // 32768 threads, 2 px each
  int bt = idx >> 11, p2 = idx & 2047;
  size_t base = (size_t)bt*CHW + p2*2;
  float s0=0.f,s1=0.f,q0=0.f,q1=0.f;
  #pragma unroll 8
  for (int c=0;c<Cc;c++){
    float2 r = *(const float2*)&g_z_r[base + (size_t)c*HW];
    float2 im = *(const float2*)&g_z_i[base + (size_t)c*HW];
    s0 += r.x + im.x; s1 += r.y + im.y;
    q0 += r.x*r.x + im.x*im.x; q1 += r.y*r.y + im.y*im.y;
  }
  float m0 = s0*(1.f/64.f), m1 = s1*(1.f/64.f);
  float i0 = rsqrtf(q0*(1.f/64.f) - m0*m0 + 1e-5f);
  float i1 = rsqrtf(q1*(1.f/64.f) - m1*m1 + 1e-5f);
  int lane = threadIdx.x & 31, wid = threadIdx.x >> 5;
  for (int c=0;c<Cc;c++){
    float2 r = *(const float2*)&g_z_r[base + (size_t)c*HW];
    float2 im = *(const float2*)&g_z_i[base + (size_t)c*HW];
    float gr = lg[c], br = lb[c], gi = lg[c+32], bi = lb[c+32];
    float nr0 = (r.x-m0)*i0*gr+br, nr1 = (r.y-m1)*i1*gr+br;
    float ni0 = (im.x-m0)*i0*gi+bi, ni1 = (im.y-m1)*i1*gi+bi;
    *(float2*)&g_znc_r[base + (size_t)c*HW] = make_float2(nr0, nr1);
    *(float2*)&g_znc_i[base + (size_t)c*HW] = make_float2(ni0, ni1);
    float mag = sqrtf(nr0*nr0 + ni0*ni0) + sqrtf(nr1*nr1 + ni1*ni1);
    #pragma unroll
    for (int off=16; off; off>>=1) mag += __shfl_xor_sync(0xffffffffu, mag, off);
    if (lane == 0) cacc2[wid][c] = mag;
  }
  __syncthreads();
  if (threadIdx.x < 32){
    float s = 0.f;
    #pragma unroll
    for (int w=0; w<8; w++) s += cacc2[w][threadIdx.x];
    g_ctxp[blockIdx.x*32 + threadIdx.x] = s;    // blockIdx = bt*8 + sub
  }
}

// ---------------- K5: evo + input gain (small) ----------------
__global__ void k_gates(const float* __restrict__ dt, const float* __restrict__ alpha,
                        const float* __restrict__ omega, const float* __restrict__ gW,
                        const float* __restrict__ gb){
  int i = threadIdx.x; if (i >= NBT*Cc) return;
  int bt = i >> 5, c = i & 31;
  float dtv = dt[bt];
  float a = alpha[c];
  float sp = (a > 0.f) ? a + log1pf(expf(-a)) : log1pf(expf(a));
  float er = expf(-dtv*sp);
  float sn, cs; sincosf(dtv*omega[c], &sn, &cs);
  g_evo[i] = make_float2(er*cs, er*sn);
  float acc = gb[c];
  for (int k=0;k<32;k++){
    float ctx = 0.f;
    for (int sb=0; sb<8; sb++) ctx += g_ctxp[(bt*8+sb)*32 + k];
    acc += (ctx * (1.f/4096.f)) * gW[k*32 + c];
  }
  g_gain[i] = 1.f/(1.f + expf(-acc));
}

// ---------------- K6: time scan + threefry noise + residual ----------------
__global__ void k_scan(const float* __restrict__ dt, const float* __restrict__ sigma,
                       uint32_t k1a, uint32_t k1b, uint32_t k2a, uint32_t k2b){
  int gid = blockIdx.x*256 + threadIdx.x;
  int b = gid / (Cc*HW); int rem = gid - b*Cc*HW; int c = rem >> 12; int px = rem & 4095;
  float hr=0.f, hi=0.f;
  float sg = sigma[c];
  for (int t=0;t<Tt;t++){
    int btc = (b*Tt + t)*Cc + c;
    size_t base = (size_t)btc*HW + px;
    float2 e = g_evo[btc];
    float gn = g_gain[btc];
    float ur = g_znc_r[base]*gn, ui = g_znc_i[base]*gn;
    float nhr = e.x*hr - e.y*hi + ur;
    float nhi = e.x*hi + e.y*hr + ui;
    hr = nhr; hi = nhi;
    float sc = sg * sqrtf(dt[b*Tt+t] + 1e-6f);
    float er = tf_normal(k1a, k1b, (uint32_t)base);
    float ei = tf_normal(k2a, k2b, (uint32_t)base);
    g_x2_r[base] = hr + sc*er + g_z_r[base];
    g_x2_i[base] = hi + sc*ei + g_z_i[base];
  }
}

// ---------------- K7: fused MLP (X@W1 -> GELU -> @W2 -> +b2 +residual -> out) ----------------
// dynamic smem layout (floats):
//   Xs  [64][128]        8192
//   Hs  [64][132] (pad)  8448
//   Wc  [64][64]         4096
//   Wc2 [64][64]         4096
#define MLP_SMEM_FLOATS (8192 + 8448 + 4096 + 4096)
__global__ void k_mlp(const float* __restrict__ w1, const float* __restrict__ b1,
                      const float* __restrict__ w2, const float* __restrict__ b2,
                      float* __restrict__ out){
  extern __shared__ float smemf[];
  float* Xs  = smemf;
  float* Hs  = smemf + 8192;
  float* Wc  = smemf + 8192 + 8448;
  float* Wc2 = smemf + 8192 + 8448 + 4096;
  int m0 = blockIdx.x*128;
  int bt = m0 >> 12, px0 = m0 & 4095;
  int tid = threadIdx.x;
  // load X tile [64k][128m]
  for (int idx=tid; idx<8192; idx+=256){
    int m = idx & 127, k = idx >> 7;
    const float* plane = (k < 32) ? g_x2_r : g_x2_i;
    Xs[k*128 + m] = plane[((size_t)bt*Cc + (k & 31))*HW + px0 + m];
  }
  int tmg = tid & 15, tng = tid >> 4;   // m-pair group, n group
  u64t oacc[4][4];
  #pragma unroll
  for (int i=0;i<4;i++)
    #pragma unroll
    for (int j=0;j<4;j++) oacc[i][j] = 0ull;

  for (int nc=0; nc<4; nc++){
    __syncthreads();   // protect Wc/Wc2/Hs reuse
    for (int idx=tid; idx<4096; idx+=256){
      int n = idx & 63, k = idx >> 6;
      Wc[k*64 + n] = w1[(size_t)k*256 + nc*64 + n];
    }
    for (int idx=tid; idx<4096; idx+=256){
      int n2 = idx & 63, k2 = idx >> 6;
      Wc2[k2*64 + n2] = w2[(size_t)(nc*64 + k2)*64 + n2];
    }
    __syncthreads();
    // stage A: H = X @ Wc  (pack over m)
    u64t hacc[4][4];
    #pragma unroll
    for (int i=0;i<4;i++)
      #pragma unroll
      for (int j=0;j<4;j++) hacc[i][j] = 0ull;
    for (int k=0;k<64;k++){
      float4 wv = *(const float4*)&Wc[k*64 + tng*4];
      u64t w0 = pk2(wv.x, wv.x), w1p = pk2(wv.y, wv.y);
      u64t w2p = pk2(wv.z, wv.z), w3p = pk2(wv.w, wv.w);
      #pragma unroll
      for (int i=0;i<4;i++){
        u64t xx = *(const u64t*)&Xs[k*128 + 2*(tmg + 16*i)];
        fma2(hacc[i][0], xx, w0);
        fma2(hacc[i][1], xx, w1p);
        fma2(hacc[i][2], xx, w2p);
        fma2(hacc[i][3], xx, w3p);
      }
    }
    // bias + GELU, stage into Hs[n][m] (stride 132)
    #pragma unroll
    for (int j=0;j<4;j++){
      int n = tng*4 + j;
      float bb = b1[nc*64 + n];
      #pragma unroll
      for (int i=0;i<4;i++){
        float a0, a1; upk2(hacc[i][j], a0, a1);
        a0 += bb; a1 += bb;
        float g0 = 0.5f*a0*(1.f + tanhf(0.7978845608028654f*(a0 + 0.044715f*a0*a0*a0)));
        float g1 = 0.5f*a1*(1.f + tanhf(0.7978845608028654f*(a1 + 0.044715f*a1*a1*a1)));
        *(float2*)&Hs[n*132 + 2*(tmg + 16*i)] = make_float2(g0, g1);
      }
    }
    __syncthreads();
    // stage B: out += H @ Wc2
    for (int k2=0;k2<64;k2++){
      float4 wv = *(const float4*)&Wc2[k2*64 + tng*4];
      u64t w0 = pk2(wv.x, wv.x), w1p = pk2(wv.y, wv.y);
      u64t w2p = pk2(wv.z, wv.z), w3p = pk2(wv.w, wv.w);
      #pragma unroll
      for (int i=0;i<4;i++){
        u64t hh = *(const u64t*)&Hs[k2*132 + 2*(tmg + 16*i)];
        fma2(oacc[i][0], hh, w0);
        fma2(oacc[i][1], hh, w1p);
        fma2(oacc[i][2], hh, w2p);
        fma2(oacc[i][3], hh, w3p);
      }
    }
  }
  // epilogue: + b2 + residual, write out
  #pragma unroll
  for (int j=0;j<4;j++){
    int n2 = tng*4 + j;
    float bb = b2[n2];
    const float* resp = (n2 < 32) ? &g_x2_r[((size_t)bt*Cc + n2)*HW]
                                  : &g_x2_i[((size_t)bt*Cc + (n2-32))*HW];
    #pragma unroll
    for (int i=0;i<4;i++){
      int m = px0 + 2*(tmg + 16*i);
      float a0, a1; upk2(oacc[i][j], a0, a1);
      float2 rv = *(const float2*)&resp[m];
      *(float2*)&out[((size_t)bt*64 + n2)*HW + m] = make_float2(a0 + bb + rv.x, a1 + bb + rv.y);
    }
  }
}

// ---------------- host launcher ----------------
extern "C" void kernel_launch(void* const* d_in, const int* in_sizes, int n_in,
                              void* d_out, int out_size){
  const float* x_real = (const float*)d_in[0];
  const float* x_imag = (const float*)d_in[1];
  const float* dt     = (const float*)d_in[2];
  const float* ln_s_g = (const float*)d_in[3];
  const float* ln_s_b = (const float*)d_in[4];
  const float* cliffw = (const float*)d_in[5];
  const float* cliffb = (const float*)d_in[6];
  const float* specwr = (const float*)d_in[7];
  const float* specwi = (const float*)d_in[8];
  const float* gate   = (const float*)d_in[9];
  const float* ln_t_g = (const float*)d_in[10];
  const float* ln_t_b = (const float*)d_in[11];
  const float* alpha  = (const float*)d_in[12];
  const float* omega  = (const float*)d_in[13];
  const float* gain_W = (const float*)d_in[14];
  const float* gain_b = (const float*)d_in[15];
  const float* sigma  = (const float*)d_in[16];
  const float* pw1    = (const float*)d_in[17];
  const float* pb1    = (const float*)d_in[18];
  const float* pw2    = (const float*)d_in[19];
  const float* pb2    = (const float*)d_in[20];
  float* out = (float*)d_out;

  uint32_t k1a,k1b,k2a,k2b;
  tf_block(0u, 42u, 0u, 0u, &k1a, &k1b);   // keys[0]
  tf_block(0u, 42u, 0u, 1u, &k2a, &k2b);   // keys[1]

  static int smem_set = 0;
  if (!smem_set){
    cudaFuncSetAttribute(k_mlp, cudaFuncAttributeMaxDynamicSharedMemorySize,
                         MLP_SMEM_FLOATS*4);
    smem_set = 1;
  }

  k_ln_spatial<<<128, 256>>>(x_real, x_imag, ln_s_g, ln_s_b);
  k_conv<<<dim3(4, 8, 16), 256>>>(cliffw, cliffb);
  k_spec<<<512, 256>>>(specwr, specwi, gate, x_real, x_imag);
  k_ln_temporal<<<128, 256>>>(ln_t_g, ln_t_b);
  k_gates<<<1, 512>>>(dt, alpha, omega, gain_W, gain_b);
  k_scan<<<1024, 256>>>(dt, sigma, k1a, k1b, k2a, k2b);
  k_mlp<<<512, 256, MLP_SMEM_FLOATS*4>>>(pw1, pb1, pw2, pb2, out);
}

// round 5
// speedup vs baseline: 2.1334x; 1.4999x over previous
#include <cuda_runtime.h>
#include <stdint.h>
#include <math.h>

#define Bb 2
#define Tt 8
#define Cc 32
#define HW 4096
#define CHW (Cc*HW)
#define NBT (Bb*Tt)
#define NEL (NBT*CHW)         // 2097152
#define NTOK (NBT*HW)         // 65536

// ---------------- scratch (device globals; no allocation) ----------------
__device__ float g_xnc_r[NEL], g_xnc_i[NEL];
__device__ float g_conv[NBT*64*HW];
__device__ float g_z_r[NEL], g_z_i[NEL];
__device__ float g_znc_r[NEL], g_znc_i[NEL];
__device__ float g_x2_r[NEL], g_x2_i[NEL];
__device__ float g_ctxp[128*32];
__device__ float g_gain[NBT*Cc];
__device__ float2 g_evo[NBT*Cc];
__device__ float g_wT[9*64*64];       // [tap][ic][oc], tf32-rounded

// ---------------- packed f32x2 helpers ----------------
typedef unsigned long long u64t;
__device__ __forceinline__ u64t pk2(float lo, float hi){
  u64t r; asm("mov.b64 %0, {%1, %2};" : "=l"(r) : "f"(lo), "f"(hi)); return r;
}
__device__ __forceinline__ void upk2(u64t v, float& lo, float& hi){
  asm("mov.b64 {%0, %1}, %2;" : "=f"(lo), "=f"(hi) : "l"(v));
}
__device__ __forceinline__ void fma2(u64t& d, u64t a, u64t b){
  asm("fma.rn.f32x2 %0, %1, %2, %3;" : "=l"(d) : "l"(a), "l"(b), "l"(d));
}

// ---------------- tf32 helpers ----------------
__device__ __forceinline__ float to_tf32(float x){
  float r; asm("cvt.rna.tf32.f32 %0, %1;" : "=f"(r) : "f"(x)); return r;
}
__device__ __forceinline__ void mma_tf32(float c[4], uint32_t a0, uint32_t a1,
                                         uint32_t a2, uint32_t a3,
                                         uint32_t b0, uint32_t b1){
  asm volatile("mma.sync.aligned.m16n8k8.row.col.f32.tf32.tf32.f32 "
    "{%0,%1,%2,%3}, {%4,%5,%6,%7}, {%8,%9}, {%0,%1,%2,%3};"
    : "+f"(c[0]), "+f"(c[1]), "+f"(c[2]), "+f"(c[3])
    : "r"(a0), "r"(a1), "r"(a2), "r"(a3), "r"(b0), "r"(b1));
}

// ---------------- threefry2x32 (JAX partitionable-mode compatible) ----------------
__host__ __device__ __forceinline__ uint32_t tf_rotl(uint32_t x, int r){ return (x<<r)|(x>>(32-r)); }
__host__ __device__ __forceinline__ void tf_block(uint32_t k0,uint32_t k1,uint32_t x0,uint32_t x1,
                                                  uint32_t* o0,uint32_t* o1){
  uint32_t ks2 = k0 ^ k1 ^ 0x1BD11BDAu;
  x0 += k0; x1 += k1;
#define R4(a,b,c,d) x0+=x1; x1=tf_rotl(x1,a); x1^=x0; x0+=x1; x1=tf_rotl(x1,b); x1^=x0; \
                    x0+=x1; x1=tf_rotl(x1,c); x1^=x0; x0+=x1; x1=tf_rotl(x1,d); x1^=x0;
  R4(13,15,26,6)  x0+=k1;  x1+=ks2+1u;
  R4(17,29,16,24) x0+=ks2; x1+=k0+2u;
  R4(13,15,26,6)  x0+=k0;  x1+=k1+3u;
  R4(17,29,16,24) x0+=k1;  x1+=ks2+4u;
  R4(13,15,26,6)  x0+=ks2; x1+=k0+5u;
#undef R4
  *o0=x0; *o1=x1;
}

__device__ __forceinline__ float tf_normal(uint32_t k0, uint32_t k1, uint32_t j){
  uint32_t o0,o1;
  tf_block(k0,k1, 0u, j, &o0,&o1);
  uint32_t bits = o0 ^ o1;
  const float lo = -0.99999994f;
  float f = __uint_as_float((bits>>9) | 0x3f800000u) - 1.0f;
  float u = f * (1.0f - lo) + lo;
  u = fmaxf(lo, u);
  return 1.41421356237309515f * erfinvf(u);
}

// ---------------- K0: weight transpose + tf32 round ----------------
__global__ void k_wprep(const float* __restrict__ cw){
  int i = blockIdx.x*256 + threadIdx.x;
  if (i >= 9*64*64) return;
  int tap = i >> 12, rem = i & 4095, ic = rem >> 6, oc = rem & 63;
  g_wT[i] = to_tf32(cw[((size_t)oc*64 + ic)*9 + tap]);
}

// ---------------- K1: spatial complex layernorm (2 px / thread) ----------------
__global__ void k_ln_spatial(const float* __restrict__ xr, const float* __restrict__ xi,
                             const float* __restrict__ lg, const float* __restrict__ lb){
  int idx = blockIdx.x*256 + threadIdx.x;
  int bt = idx >> 11, p2 = idx & 2047;
  size_t base = (size_t)bt*CHW + p2*2;
  float s0=0.f,s1=0.f,q0=0.f,q1=0.f;
  #pragma unroll 8
  for (int c=0;c<Cc;c++){
    float2 r = *(const float2*)&xr[base + (size_t)c*HW];
    float2 im = *(const float2*)&xi[base + (size_t)c*HW];
    s0 += r.x + im.x; s1 += r.y + im.y;
    q0 += r.x*r.x + im.x*im.x; q1 += r.y*r.y + im.y*im.y;
  }
  float m0 = s0*(1.f/64.f), m1 = s1*(1.f/64.f);
  float i0 = rsqrtf(q0*(1.f/64.f) - m0*m0 + 1e-5f);
  float i1 = rsqrtf(q1*(1.f/64.f) - m1*m1 + 1e-5f);
  #pragma unroll 8
  for (int c=0;c<Cc;c++){
    float2 r = *(const float2*)&xr[base + (size_t)c*HW];
    float2 im = *(const float2*)&xi[base + (size_t)c*HW];
    float gr = lg[c], br = lb[c], gi = lg[c+32], bi = lb[c+32];
    *(float2*)&g_xnc_r[base + (size_t)c*HW] = make_float2((r.x-m0)*i0*gr+br, (r.y-m1)*i1*gr+br);
    *(float2*)&g_xnc_i[base + (size_t)c*HW] = make_float2((im.x-m0)*i0*gi+bi, (im.y-m1)*i1*gi+bi);
  }
}

// ---------------- K2: Clifford 3x3 conv — implicit GEMM on mma.sync tf32 ----------------
// block: (ytile 0..31, bt 0..15); 256 threads = 8 warps.
// M = 128 px (2 image rows), N = 64 oc, K = 64 ic per tap, 9 taps.
#define CONV_SMEM_FLOATS (64*264 + 64*72)
__global__ void k_conv(const float* __restrict__ cb){
  extern __shared__ float cs[];
  float* Ain = cs;             // [ic][rr=4][cc=66], tf32-rounded
  float* Bw  = cs + 64*264;    // [ic][72-padded oc]
  int y0 = blockIdx.x*2, bt = blockIdx.y;
  int tid = threadIdx.x, lane = tid & 31, w = tid >> 5;
  int y_local = w >> 2, x0 = (w & 3)*16;
  // stage A once (halo + zero pad)
  for (int idx=tid; idx<64*264; idx+=256){
    int ic = idx/264, rem = idx - ic*264, rr = rem/66, cc = rem - rr*66;
    int gy = y0 - 1 + rr, gx = cc - 1;
    const float* plane = (ic < 32 ? g_xnc_r : g_xnc_i) + ((size_t)bt*Cc + (ic & 31))*HW;
    float v = (gy>=0 && gy<64 && gx>=0 && gx<64) ? plane[gy*64+gx] : 0.f;
    Ain[idx] = to_tf32(v);
  }
  float acc[8][4];
  #pragma unroll
  for (int nt=0;nt<8;nt++)
    #pragma unroll
    for (int j=0;j<4;j++) acc[nt][j] = 0.f;

  int lm = lane >> 2, lk = lane & 3;   // fragment row/col components
  for (int tap=0; tap<9; tap++){
    __syncthreads();                    // A ready / Bw reuse safe
    for (int idx=tid; idx<4096; idx+=256){
      int ic = idx >> 6, oc = idx & 63;
      Bw[ic*72 + oc] = g_wT[(tap << 12) + idx];
    }
    __syncthreads();
    int rr = y_local + tap/3;
    int ccb = x0 + (tap - (tap/3)*3) + lm;
    #pragma unroll
    for (int ch=0; ch<8; ch++){
      const float* ap = &Ain[(ch*8 + lk)*264 + rr*66 + ccb];
      uint32_t a0 = __float_as_uint(ap[0]);
      uint32_t a1 = __float_as_uint(ap[8]);
      uint32_t a2 = __float_as_uint(ap[4*264]);
      uint32_t a3 = __float_as_uint(ap[4*264 + 8]);
      const float* bp = &Bw[(ch*8 + lk)*72 + lm];
      #pragma unroll
      for (int nt=0; nt<8; nt++){
        uint32_t b0 = __float_as_uint(bp[nt*8]);
        uint32_t b1 = __float_as_uint(bp[4*72 + nt*8]);
        mma_tf32(acc[nt], a0, a1, a2, a3, b0, b1);
      }
    }
  }
  // epilogue: c0/c1 -> (x, oc/oc+1); c2/c3 -> (x+8, oc/oc+1)
  int yy = y0 + y_local;
  int x = x0 + lm;
  #pragma unroll
  for (int nt=0; nt<8; nt++){
    int oc = nt*8 + 2*lk;
    float bv0 = cb[oc], bv1 = cb[oc+1];
    size_t o0 = (((size_t)bt*64 + oc)*64 + yy)*64;
    g_conv[o0 + x]            = acc[nt][0] + bv0;
    g_conv[o0 + 4096 + x]     = acc[nt][1] + bv1;
    g_conv[o0 + x + 8]        = acc[nt][2] + bv0;
    g_conv[o0 + 4096 + x + 8] = acc[nt][3] + bv1;
  }
}

// ---------------- K3: spectral branch ----------------
__device__ __forceinline__ float2 cmul(float2 a, float2 b){
  return make_float2(a.x*b.x - a.y*b.y, a.x*b.y + a.y*b.x);
}
__device__ __forceinline__ void fft8(float2 a[8], float sgn){
  const float C1 = 0.70710678118654752440f;
  float2 w1 = make_float2(C1, sgn*C1);
  float2 w2 = make_float2(0.f, sgn);
  float2 w3 = make_float2(-C1, sgn*C1);
  float2 t;
  t = make_float2(a[0].x-a[4].x, a[0].y-a[4].y); a[0].x+=a[4].x; a[0].y+=a[4].y; a[4]=t;
  t = make_float2(a[1].x-a[5].x, a[1].y-a[5].y); a[1].x+=a[5].x; a[1].y+=a[5].y; a[5]=cmul(t,w1);
  t = make_float2(a[2].x-a[6].x, a[2].y-a[6].y); a[2].x+=a[6].x; a[2].y+=a[6].y; a[6]=cmul(t,w2);
  t = make_float2(a[3].x-a[7].x, a[3].y-a[7].y); a[3].x+=a[7].x; a[3].y+=a[7].y; a[7]=cmul(t,w3);
  #pragma unroll
  for (int g=0; g<8; g+=4){
    t = make_float2(a[g].x-a[g+2].x, a[g].y-a[g+2].y); a[g].x+=a[g+2].x; a[g].y+=a[g+2].y; a[g+2]=t;
    t = make_float2(a[g+1].x-a[g+3].x, a[g+1].y-a[g+3].y); a[g+1].x+=a[g+3].x; a[g+1].y+=a[g+3].y; a[g+3]=cmul(t,w2);
  }
  #pragma unroll
  for (int p=0; p<8; p+=2){
    t = make_float2(a[p].x-a[p+1].x, a[p].y-a[p+1].y); a[p].x+=a[p+1].x; a[p].y+=a[p+1].y; a[p+1]=t;
  }
}
__device__ __forceinline__ void fft64_line(float2* p, int st, int b8,
                                           const float2* __restrict__ tw, float sgn, bool conj_tw){
  const int rev[8] = {0,4,2,6,1,5,3,7};
  float2 a[8];
  #pragma unroll
  for (int j=0;j<8;j++) a[j] = p[(8*j + b8)*st];
  fft8(a, sgn);
  #pragma unroll
  for (int c=0;c<8;c++){
    float2 t = tw[(b8*c) & 63];
    if (conj_tw) t.y = -t.y;
    p[(8*c + b8)*st] = cmul(a[rev[c]], t);
  }
  __syncwarp();
  #pragma unroll
  for (int j=0;j<8;j++) a[j] = p[(8*b8 + j)*st];
  fft8(a, sgn);
  __syncwarp();
  #pragma unroll
  for (int d=0;d<8;d++) p[(b8 + 8*d)*st] = a[rev[d]];
  __syncwarp();
}

__global__ void k_spec(const float* __restrict__ swr, const float* __restrict__ swi,
                       const float* __restrict__ gate_p,
                       const float* __restrict__ xr, const float* __restrict__ xi){
  __shared__ float2 sm[64*65];
  __shared__ float2 tw[64];
  int blk = blockIdx.x; int bt = blk >> 5; int c = blk & 31;
  int tid = threadIdx.x;
  if (tid < 64){
    float sv, cv; sincosf(-6.283185307179586f * (float)tid / 64.f, &sv, &cv);
    tw[tid] = make_float2(cv, sv);
  }
  size_t base = ((size_t)bt*Cc + c)*HW;
  for (int i=tid;i<HW;i+=256)
    sm[(i>>6)*65 + (i&63)] = make_float2(g_xnc_r[base+i], g_xnc_i[base+i]);
  __syncthreads();
  int oct = tid >> 3, b8 = tid & 7;
  for (int rep=0; rep<2; rep++) fft64_line(sm + (oct+32*rep)*65, 1, b8, tw, -1.f, false);
  __syncthreads();
  for (int rep=0; rep<2; rep++) fft64_line(sm + (oct+32*rep), 65, b8, tw, -1.f, false);
  __syncthreads();
  size_t coff = (size_t)c*HW;
  for (int i=tid;i<HW;i+=256){
    int h=i>>6, w=i&63;
    sm[h*65+w] = cmul(sm[h*65+w], make_float2(swr[coff+i], swi[coff+i]));
  }
  __syncthreads();
  for (int rep=0; rep<2; rep++) fft64_line(sm + (oct+32*rep)*65, 1, b8, tw, 1.f, true);
  __syncthreads();
  for (int rep=0; rep<2; rep++) fft64_line(sm + (oct+32*rep), 65, b8, tw, 1.f, true);
  __syncthreads();
  float g = gate_p[0];
  const float invN = 1.f/4096.f;
  for (int i=tid;i<HW;i+=256){
    float2 sp = sm[(i>>6)*65 + (i&63)];
    float cr = g_conv[((size_t)bt*64 + c)*HW + i];
    float ci = g_conv[((size_t)bt*64 + 32 + c)*HW + i];
    g_z_r[base+i] = g*cr + (1.f-g)*(sp.x*invN) + xr[base+i];
    g_z_i[base+i] = g*ci + (1.f-g)*(sp.y*invN) + xi[base+i];
  }
}

// ---------------- K4: temporal layernorm + ctx partials (2 px / thread) ----------------
__global__ void k_ln_temporal(const float* __restrict__ lg, const float* __restrict__ lb){
  __shared__ float cacc2[8][32];
  int idx = blockIdx.x*256 + threadIdx.x;
  int bt = idx >> 11, p2 = idx & 2047;
  size_t base = (size_t)bt*CHW + p2*2;
  float s0=0.f,s1=0.f,q0=0.f,q1=0.f;
  #pragma unroll 8
  for (int c=0;c<Cc;c++){
    float2 r = *(const float2*)&g_z_r[base + (size_t)c*HW];
    float2 im = *(const float2*)&g_z_i[base + (size_t)c*HW];
    s0 += r.x + im.x; s1 += r.y + im.y;
    q0 += r.x*r.x + im.x*im.x; q1 += r.y*r.y + im.y*im.y;
  }
  float m0 = s0*(1.f/64.f), m1 = s1*(1.f/64.f);
  float i0 = rsqrtf(q0*(1.f/64.f) - m0*m0 + 1e-5f);
  float i1 = rsqrtf(q1*(1.f/64.f) - m1*m1 + 1e-5f);
  int lane = threadIdx.x & 31, wid = threadIdx.x >> 5;
  for (int c=0;c<Cc;c++){
    float2 r = *(const float2*)&g_z_r[base + (size_t)c*HW];
    float2 im = *(const float2*)&g_z_i[base + (size_t)c*HW];
    float gr = lg[c], br = lb[c], gi = lg[c+32], bi = lb[c+32];
    float nr0 = (r.x-m0)*i0*gr+br, nr1 = (r.y-m1)*i1*gr+br;
    float ni0 = (im.x-m0)*i0*gi+bi, ni1 = (im.y-m1)*i1*gi+bi;
    *(float2*)&g_znc_r[base + (size_t)c*HW] = make_float2(nr0, nr1);
    *(float2*)&g_znc_i[base + (size_t)c*HW] = make_float2(ni0, ni1);
    float mag = sqrtf(nr0*nr0 + ni0*ni0) + sqrtf(nr1*nr1 + ni1*ni1);
    #pragma unroll
    for (int off=16; off; off>>=1) mag += __shfl_xor_sync(0xffffffffu, mag, off);
    if (lane == 0) cacc2[wid][c] = mag;
  }
  __syncthreads();
  if (threadIdx.x < 32){
    float s = 0.f;
    #pragma unroll
    for (int w=0; w<8; w++) s += cacc2[w][threadIdx.x];
    g_ctxp[blockIdx.x*32 + threadIdx.x] = s;
  }
}

// ---------------- K5: evo + input gain (small) ----------------
__global__ void k_gates(const float* __restrict__ dt, const float* __restrict__ alpha,
                        const float* __restrict__ omega, const float* __restrict__ gW,
                        const float* __restrict__ gb){
  int i = threadIdx.x; if (i >= NBT*Cc) return;
  int bt = i >> 5, c = i & 31;
  float dtv = dt[bt];
  float a = alpha[c];
  float sp = (a > 0.f) ? a + log1pf(expf(-a)) : log1pf(expf(a));
  float er = expf(-dtv*sp);
  float sn, cs; sincosf(dtv*omega[c], &sn, &cs);
  g_evo[i] = make_float2(er*cs, er*sn);
  float acc = gb[c];
  for (int k=0;k<32;k++){
    float ctx = 0.f;
    for (int sb=0; sb<8; sb++) ctx += g_ctxp[(bt*8+sb)*32 + k];
    acc += (ctx * (1.f/4096.f)) * gW[k*32 + c];
  }
  g_gain[i] = 1.f/(1.f + expf(-acc));
}

// ---------------- K6: time scan + threefry noise + residual ----------------
__global__ void k_scan(const float* __restrict__ dt, const float* __restrict__ sigma,
                       uint32_t k1a, uint32_t k1b, uint32_t k2a, uint32_t k2b){
  int gid = blockIdx.x*256 + threadIdx.x;
  int b = gid / (Cc*HW); int rem = gid - b*Cc*HW; int c = rem >> 12; int px = rem & 4095;
  float hr=0.f, hi=0.f;
  float sg = sigma[c];
  for (int t=0;t<Tt;t++){
    int btc = (b*Tt + t)*Cc + c;
    size_t base = (size_t)btc*HW + px;
    float2 e = g_evo[btc];
    float gn = g_gain[btc];
    float ur = g_znc_r[base]*gn, ui = g_znc_i[base]*gn;
    float nhr = e.x*hr - e.y*hi + ur;
    float nhi = e.x*hi + e.y*hr + ui;
    hr = nhr; hi = nhi;
    float sc = sg * sqrtf(dt[b*Tt+t] + 1e-6f);
    float er = tf_normal(k1a, k1b, (uint32_t)base);
    float ei = tf_normal(k2a, k2b, (uint32_t)base);
    g_x2_r[base] = hr + sc*er + g_z_r[base];
    g_x2_i[base] = hi + sc*ei + g_z_i[base];
  }
}

// ---------------- K7: fused MLP (X@W1 -> GELU -> @W2 -> +b2 +residual -> out) ----------------
#define MLP_SMEM_FLOATS (8192 + 8448 + 4096 + 4096)
__global__ void k_mlp(const float* __restrict__ w1, const float* __restrict__ b1,
                      const float* __restrict__ w2, const float* __restrict__ b2,
                      float* __restrict__ out){
  extern __shared__ float smemf[];
  float* Xs  = smemf;
  float* Hs  = smemf + 8192;
  float* Wc  = smemf + 8192 + 8448;
  float* Wc2 = smemf + 8192 + 8448 + 4096;
  int m0 = blockIdx.x*128;
  int bt = m0 >> 12, px0 = m0 & 4095;
  int tid = threadIdx.x;
  for (int idx=tid; idx<8192; idx+=256){
    int m = idx & 127, k = idx >> 7;
    const float* plane = (k < 32) ? g_x2_r : g_x2_i;
    Xs[k*128 + m] = plane[((size_t)bt*Cc + (k & 31))*HW + px0 + m];
  }
  int tmg = tid & 15, tng = tid >> 4;
  u64t oacc[4][4];
  #pragma unroll
  for (int i=0;i<4;i++)
    #pragma unroll
    for (int j=0;j<4;j++) oacc[i][j] = 0ull;

  for (int nc=0; nc<4; nc++){
    __syncthreads();
    for (int idx=tid; idx<4096; idx+=256){
      int n = idx & 63, k = idx >> 6;
      Wc[k*64 + n] = w1[(size_t)k*256 + nc*64 + n];
    }
    for (int idx=tid; idx<4096; idx+=256){
      int n2 = idx & 63, k2 = idx >> 6;
      Wc2[k2*64 + n2] = w2[(size_t)(nc*64 + k2)*64 + n2];
    }
    __syncthreads();
    u64t hacc[4][4];
    #pragma unroll
    for (int i=0;i<4;i++)
      #pragma unroll
      for (int j=0;j<4;j++) hacc[i][j] = 0ull;
    for (int k=0;k<64;k++){
      float4 wv = *(const float4*)&Wc[k*64 + tng*4];
      u64t w0 = pk2(wv.x, wv.x), w1p = pk2(wv.y, wv.y);
      u64t w2p = pk2(wv.z, wv.z), w3p = pk2(wv.w, wv.w);
      #pragma unroll
      for (int i=0;i<4;i++){
        u64t xx = *(const u64t*)&Xs[k*128 + 2*(tmg + 16*i)];
        fma2(hacc[i][0], xx, w0);
        fma2(hacc[i][1], xx, w1p);
        fma2(hacc[i][2], xx, w2p);
        fma2(hacc[i][3], xx, w3p);
      }
    }
    #pragma unroll
    for (int j=0;j<4;j++){
      int n = tng*4 + j;
      float bb = b1[nc*64 + n];
      #pragma unroll
      for (int i=0;i<4;i++){
        float a0, a1; upk2(hacc[i][j], a0, a1);
        a0 += bb; a1 += bb;
        float g0 = 0.5f*a0*(1.f + tanhf(0.7978845608028654f*(a0 + 0.044715f*a0*a0*a0)));
        float g1 = 0.5f*a1*(1.f + tanhf(0.7978845608028654f*(a1 + 0.044715f*a1*a1*a1)));
        *(float2*)&Hs[n*132 + 2*(tmg + 16*i)] = make_float2(g0, g1);
      }
    }
    __syncthreads();
    for (int k2=0;k2<64;k2++){
      float4 wv = *(const float4*)&Wc2[k2*64 + tng*4];
      u64t w0 = pk2(wv.x, wv.x), w1p = pk2(wv.y, wv.y);
      u64t w2p = pk2(wv.z, wv.z), w3p = pk2(wv.w, wv.w);
      #pragma unroll
      for (int i=0;i<4;i++){
        u64t hh = *(const u64t*)&Hs[k2*132 + 2*(tmg + 16*i)];
        fma2(oacc[i][0], hh, w0);
        fma2(oacc[i][1], hh, w1p);
        fma2(oacc[i][2], hh, w2p);
        fma2(oacc[i][3], hh, w3p);
      }
    }
  }
  #pragma unroll
  for (int j=0;j<4;j++){
    int n2 = tng*4 + j;
    float bb = b2[n2];
    const float* resp = (n2 < 32) ? &g_x2_r[((size_t)bt*Cc + n2)*HW]
                                  : &g_x2_i[((size_t)bt*Cc + (n2-32))*HW];
    #pragma unroll
    for (int i=0;i<4;i++){
      int m = px0 + 2*(tmg + 16*i);
      float a0, a1; upk2(oacc[i][j], a0, a1);
      float2 rv = *(const float2*)&resp[m];
      *(float2*)&out[((size_t)bt*64 + n2)*HW + m] = make_float2(a0 + bb + rv.x, a1 + bb + rv.y);
    }
  }
}

// ---------------- host launcher ----------------
extern "C" void kernel_launch(void* const* d_in, const int* in_sizes, int n_in,
                              void* d_out, int out_size){
  const float* x_real = (const float*)d_in[0];
  const float* x_imag = (const float*)d_in[1];
  const float* dt     = (const float*)d_in[2];
  const float* ln_s_g = (const float*)d_in[3];
  const float* ln_s_b = (const float*)d_in[4];
  const float* cliffw = (const float*)d_in[5];
  const float* cliffb = (const float*)d_in[6];
  const float* specwr = (const float*)d_in[7];
  const float* specwi = (const float*)d_in[8];
  const float* gate   = (const float*)d_in[9];
  const float* ln_t_g = (const float*)d_in[10];
  const float* ln_t_b = (const float*)d_in[11];
  const float* alpha  = (const float*)d_in[12];
  const float* omega  = (const float*)d_in[13];
  const float* gain_W = (const float*)d_in[14];
  const float* gain_b = (const float*)d_in[15];
  const float* sigma  = (const float*)d_in[16];
  const float* pw1    = (const float*)d_in[17];
  const float* pb1    = (const float*)d_in[18];
  const float* pw2    = (const float*)d_in[19];
  const float* pb2    = (const float*)d_in[20];
  float* out = (float*)d_out;

  uint32_t k1a,k1b,k2a,k2b;
  tf_block(0u, 42u, 0u, 0u, &k1a, &k1b);   // keys[0]
  tf_block(0u, 42u, 0u, 1u, &k2a, &k2b);   // keys[1]

  static int smem_set = 0;
  if (!smem_set){
    cudaFuncSetAttribute(k_mlp, cudaFuncAttributeMaxDynamicSharedMemorySize,
                         MLP_SMEM_FLOATS*4);
    cudaFuncSetAttribute(k_conv, cudaFuncAttributeMaxDynamicSharedMemorySize,
                         CONV_SMEM_FLOATS*4);
    smem_set = 1;
  }

  k_wprep<<<144, 256>>>(cliffw);
  k_ln_spatial<<<128, 256>>>(x_real, x_imag, ln_s_g, ln_s_b);
  k_conv<<<dim3(32, 16), 256, CONV_SMEM_FLOATS*4>>>(cliffb);
  k_spec<<<512, 256>>>(specwr, specwi, gate, x_real, x_imag);
  k_ln_temporal<<<128, 256>>>(ln_t_g, ln_t_b);
  k_gates<<<1, 512>>>(dt, alpha, omega, gain_W, gain_b);
  k_scan<<<1024, 256>>>(dt, sigma, k1a, k1b, k2a, k2b);
  k_mlp<<<512, 256, MLP_SMEM_FLOATS*4>>>(pw1, pb1, pw2, pb2, out);
}

// round 6
// speedup vs baseline: 2.5453x; 1.1931x over previous
#include <cuda_runtime.h>
#include <stdint.h>
#include <math.h>

#define Bb 2
#define Tt 8
#define Cc 32
#define HW 4096
#define CHW (Cc*HW)
#define NBT (Bb*Tt)
#define NEL (NBT*CHW)         // 2097152
#define NTOK (NBT*HW)         // 65536

// ---------------- scratch (device globals; no allocation) ----------------
__device__ float g_xnc_r[NEL], g_xnc_i[NEL];
__device__ float g_conv[NBT*64*HW];
__device__ float g_z_r[NEL], g_z_i[NEL];
__device__ float g_znc_r[NEL], g_znc_i[NEL];
__device__ float g_x2_r[NEL], g_x2_i[NEL];
__device__ float g_ctxp[128*32];
__device__ float g_gain[NBT*Cc];
__device__ float2 g_evo[NBT*Cc];
__device__ float g_wT[9*64*64];       // [tap][ic][oc], tf32-rounded

// ---------------- tf32 / mma helpers ----------------
__device__ __forceinline__ float to_tf32(float x){
  float r; asm("cvt.rna.tf32.f32 %0, %1;" : "=f"(r) : "f"(x)); return r;
}
__device__ __forceinline__ void mma_tf32(float c[4], uint32_t a0, uint32_t a1,
                                         uint32_t a2, uint32_t a3,
                                         uint32_t b0, uint32_t b1){
  asm volatile("mma.sync.aligned.m16n8k8.row.col.f32.tf32.tf32.f32 "
    "{%0,%1,%2,%3}, {%4,%5,%6,%7}, {%8,%9}, {%0,%1,%2,%3};"
    : "+f"(c[0]), "+f"(c[1]), "+f"(c[2]), "+f"(c[3])
    : "r"(a0), "r"(a1), "r"(a2), "r"(a3), "r"(b0), "r"(b1));
}

// ---------------- threefry2x32 (JAX partitionable-mode compatible) ----------------
__host__ __device__ __forceinline__ uint32_t tf_rotl(uint32_t x, int r){ return (x<<r)|(x>>(32-r)); }
__host__ __device__ __forceinline__ void tf_block(uint32_t k0,uint32_t k1,uint32_t x0,uint32_t x1,
                                                  uint32_t* o0,uint32_t* o1){
  uint32_t ks2 = k0 ^ k1 ^ 0x1BD11BDAu;
  x0 += k0; x1 += k1;
#define R4(a,b,c,d) x0+=x1; x1=tf_rotl(x1,a); x1^=x0; x0+=x1; x1=tf_rotl(x1,b); x1^=x0; \
                    x0+=x1; x1=tf_rotl(x1,c); x1^=x0; x0+=x1; x1=tf_rotl(x1,d); x1^=x0;
  R4(13,15,26,6)  x0+=k1;  x1+=ks2+1u;
  R4(17,29,16,24) x0+=ks2; x1+=k0+2u;
  R4(13,15,26,6)  x0+=k0;  x1+=k1+3u;
  R4(17,29,16,24) x0+=k1;  x1+=ks2+4u;
  R4(13,15,26,6)  x0+=ks2; x1+=k0+5u;
#undef R4
  *o0=x0; *o1=x1;
}

__device__ __forceinline__ float tf_normal(uint32_t k0, uint32_t k1, uint32_t j){
  uint32_t o0,o1;
  tf_block(k0,k1, 0u, j, &o0,&o1);
  uint32_t bits = o0 ^ o1;
  const float lo = -0.99999994f;
  float f = __uint_as_float((bits>>9) | 0x3f800000u) - 1.0f;
  float u = f * (1.0f - lo) + lo;
  u = fmaxf(lo, u);
  return 1.41421356237309515f * erfinvf(u);
}

// ---------------- K0: weight transpose + tf32 round ----------------
__global__ void k_wprep(const float* __restrict__ cw){
  int i = blockIdx.x*256 + threadIdx.x;
  if (i >= 9*64*64) return;
  int tap = i >> 12, rem = i & 4095, ic = rem >> 6, oc = rem & 63;
  g_wT[i] = to_tf32(cw[((size_t)oc*64 + ic)*9 + tap]);
}

// ---------------- K1: spatial complex layernorm (2 px / thread) ----------------
__global__ void k_ln_spatial(const float* __restrict__ xr, const float* __restrict__ xi,
                             const float* __restrict__ lg, const float* __restrict__ lb){
  int idx = blockIdx.x*256 + threadIdx.x;
  int bt = idx >> 11, p2 = idx & 2047;
  size_t base = (size_t)bt*CHW + p2*2;
  float s0=0.f,s1=0.f,q0=0.f,q1=0.f;
  #pragma unroll 8
  for (int c=0;c<Cc;c++){
    float2 r = *(const float2*)&xr[base + (size_t)c*HW];
    float2 im = *(const float2*)&xi[base + (size_t)c*HW];
    s0 += r.x + im.x; s1 += r.y + im.y;
    q0 += r.x*r.x + im.x*im.x; q1 += r.y*r.y + im.y*im.y;
  }
  float m0 = s0*(1.f/64.f), m1 = s1*(1.f/64.f);
  float i0 = rsqrtf(q0*(1.f/64.f) - m0*m0 + 1e-5f);
  float i1 = rsqrtf(q1*(1.f/64.f) - m1*m1 + 1e-5f);
  #pragma unroll 8
  for (int c=0;c<Cc;c++){
    float2 r = *(const float2*)&xr[base + (size_t)c*HW];
    float2 im = *(const float2*)&xi[base + (size_t)c*HW];
    float gr = lg[c], br = lb[c], gi = lg[c+32], bi = lb[c+32];
    *(float2*)&g_xnc_r[base + (size_t)c*HW] = make_float2((r.x-m0)*i0*gr+br, (r.y-m1)*i1*gr+br);
    *(float2*)&g_xnc_i[base + (size_t)c*HW] = make_float2((im.x-m0)*i0*gi+bi, (im.y-m1)*i1*gi+bi);
  }
}

// ---------------- K2: Clifford 3x3 conv — implicit GEMM on mma.sync tf32 ----------------
#define CONV_SMEM_FLOATS (64*264 + 64*72)
__global__ void k_conv(const float* __restrict__ cb){
  extern __shared__ float cs[];
  float* Ain = cs;             // [ic][rr=4][cc=66], tf32-rounded
  float* Bw  = cs + 64*264;    // [ic][72-padded oc]
  int y0 = blockIdx.x*2, bt = blockIdx.y;
  int tid = threadIdx.x, lane = tid & 31, w = tid >> 5;
  int y_local = w >> 2, x0 = (w & 3)*16;
  for (int idx=tid; idx<64*264; idx+=256){
    int ic = idx/264, rem = idx - ic*264, rr = rem/66, cc = rem - rr*66;
    int gy = y0 - 1 + rr, gx = cc - 1;
    const float* plane = (ic < 32 ? g_xnc_r : g_xnc_i) + ((size_t)bt*Cc + (ic & 31))*HW;
    float v = (gy>=0 && gy<64 && gx>=0 && gx<64) ? plane[gy*64+gx] : 0.f;
    Ain[idx] = to_tf32(v);
  }
  float acc[8][4];
  #pragma unroll
  for (int nt=0;nt<8;nt++)
    #pragma unroll
    for (int j=0;j<4;j++) acc[nt][j] = 0.f;

  int lm = lane >> 2, lk = lane & 3;
  for (int tap=0; tap<9; tap++){
    __syncthreads();
    for (int idx=tid; idx<4096; idx+=256){
      int ic = idx >> 6, oc = idx & 63;
      Bw[ic*72 + oc] = g_wT[(tap << 12) + idx];
    }
    __syncthreads();
    int rr = y_local + tap/3;
    int ccb = x0 + (tap - (tap/3)*3) + lm;
    #pragma unroll
    for (int ch=0; ch<8; ch++){
      const float* ap = &Ain[(ch*8 + lk)*264 + rr*66 + ccb];
      uint32_t a0 = __float_as_uint(ap[0]);
      uint32_t a1 = __float_as_uint(ap[8]);
      uint32_t a2 = __float_as_uint(ap[4*264]);
      uint32_t a3 = __float_as_uint(ap[4*264 + 8]);
      const float* bp = &Bw[(ch*8 + lk)*72 + lm];
      #pragma unroll
      for (int nt=0; nt<8; nt++){
        uint32_t b0 = __float_as_uint(bp[nt*8]);
        uint32_t b1 = __float_as_uint(bp[4*72 + nt*8]);
        mma_tf32(acc[nt], a0, a1, a2, a3, b0, b1);
      }
    }
  }
  int yy = y0 + y_local;
  int x = x0 + lm;
  #pragma unroll
  for (int nt=0; nt<8; nt++){
    int oc = nt*8 + 2*lk;
    float bv0 = cb[oc], bv1 = cb[oc+1];
    size_t o0 = (((size_t)bt*64 + oc)*64 + yy)*64;
    g_conv[o0 + x]            = acc[nt][0] + bv0;
    g_conv[o0 + 4096 + x]     = acc[nt][1] + bv1;
    g_conv[o0 + x + 8]        = acc[nt][2] + bv0;
    g_conv[o0 + 4096 + x + 8] = acc[nt][3] + bv1;
  }
}

// ---------------- K3: spectral branch ----------------
__device__ __forceinline__ float2 cmul(float2 a, float2 b){
  return make_float2(a.x*b.x - a.y*b.y, a.x*b.y + a.y*b.x);
}
__device__ __forceinline__ void fft8(float2 a[8], float sgn){
  const float C1 = 0.70710678118654752440f;
  float2 w1 = make_float2(C1, sgn*C1);
  float2 w2 = make_float2(0.f, sgn);
  float2 w3 = make_float2(-C1, sgn*C1);
  float2 t;
  t = make_float2(a[0].x-a[4].x, a[0].y-a[4].y); a[0].x+=a[4].x; a[0].y+=a[4].y; a[4]=t;
  t = make_float2(a[1].x-a[5].x, a[1].y-a[5].y); a[1].x+=a[5].x; a[1].y+=a[5].y; a[5]=cmul(t,w1);
  t = make_float2(a[2].x-a[6].x, a[2].y-a[6].y); a[2].x+=a[6].x; a[2].y+=a[6].y; a[6]=cmul(t,w2);
  t = make_float2(a[3].x-a[7].x, a[3].y-a[7].y); a[3].x+=a[7].x; a[3].y+=a[7].y; a[7]=cmul(t,w3);
  #pragma unroll
  for (int g=0; g<8; g+=4){
    t = make_float2(a[g].x-a[g+2].x, a[g].y-a[g+2].y); a[g].x+=a[g+2].x; a[g].y+=a[g+2].y; a[g+2]=t;
    t = make_float2(a[g+1].x-a[g+3].x, a[g+1].y-a[g+3].y); a[g+1].x+=a[g+3].x; a[g+1].y+=a[g+3].y; a[g+3]=cmul(t,w2);
  }
  #pragma unroll
  for (int p=0; p<8; p+=2){
    t = make_float2(a[p].x-a[p+1].x, a[p].y-a[p+1].y); a[p].x+=a[p+1].x; a[p].y+=a[p+1].y; a[p+1]=t;
  }
}
__device__ __forceinline__ void fft64_line(float2* p, int st, int b8,
                                           const float2* __restrict__ tw, float sgn, bool conj_tw){
  const int rev[8] = {0,4,2,6,1,5,3,7};
  float2 a[8];
  #pragma unroll
  for (int j=0;j<8;j++) a[j] = p[(8*j + b8)*st];
  fft8(a, sgn);
  #pragma unroll
  for (int c=0;c<8;c++){
    float2 t = tw[(b8*c) & 63];
    if (conj_tw) t.y = -t.y;
    p[(8*c + b8)*st] = cmul(a[rev[c]], t);
  }
  __syncwarp();
  #pragma unroll
  for (int j=0;j<8;j++) a[j] = p[(8*b8 + j)*st];
  fft8(a, sgn);
  __syncwarp();
  #pragma unroll
  for (int d=0;d<8;d++) p[(b8 + 8*d)*st] = a[rev[d]];
  __syncwarp();
}

__global__ void k_spec(const float* __restrict__ swr, const float* __restrict__ swi,
                       const float* __restrict__ gate_p,
                       const float* __restrict__ xr, const float* __restrict__ xi){
  __shared__ float2 sm[64*65];
  __shared__ float2 tw[64];
  int blk = blockIdx.x; int bt = blk >> 5; int c = blk & 31;
  int tid = threadIdx.x;
  if (tid < 64){
    float sv, cv; sincosf(-6.283185307179586f * (float)tid / 64.f, &sv, &cv);
    tw[tid] = make_float2(cv, sv);
  }
  size_t base = ((size_t)bt*Cc + c)*HW;
  for (int i=tid;i<HW;i+=256)
    sm[(i>>6)*65 + (i&63)] = make_float2(g_xnc_r[base+i], g_xnc_i[base+i]);
  __syncthreads();
  int oct = tid >> 3, b8 = tid & 7;
  for (int rep=0; rep<2; rep++) fft64_line(sm + (oct+32*rep)*65, 1, b8, tw, -1.f, false);
  __syncthreads();
  for (int rep=0; rep<2; rep++) fft64_line(sm + (oct+32*rep), 65, b8, tw, -1.f, false);
  __syncthreads();
  size_t coff = (size_t)c*HW;
  for (int i=tid;i<HW;i+=256){
    int h=i>>6, w=i&63;
    sm[h*65+w] = cmul(sm[h*65+w], make_float2(swr[coff+i], swi[coff+i]));
  }
  __syncthreads();
  for (int rep=0; rep<2; rep++) fft64_line(sm + (oct+32*rep)*65, 1, b8, tw, 1.f, true);
  __syncthreads();
  for (int rep=0; rep<2; rep++) fft64_line(sm + (oct+32*rep), 65, b8, tw, 1.f, true);
  __syncthreads();
  float g = gate_p[0];
  const float invN = 1.f/4096.f;
  for (int i=tid;i<HW;i+=256){
    float2 sp = sm[(i>>6)*65 + (i&63)];
    float cr = g_conv[((size_t)bt*64 + c)*HW + i];
    float ci = g_conv[((size_t)bt*64 + 32 + c)*HW + i];
    g_z_r[base+i] = g*cr + (1.f-g)*(sp.x*invN) + xr[base+i];
    g_z_i[base+i] = g*ci + (1.f-g)*(sp.y*invN) + xi[base+i];
  }
}

// ---------------- K4: temporal layernorm + ctx partials (2 px / thread) ----------------
__global__ void k_ln_temporal(const float* __restrict__ lg, const float* __restrict__ lb){
  __shared__ float cacc2[8][32];
  int idx = blockIdx.x*256 + threadIdx.x;
  int bt = idx >> 11, p2 = idx & 2047;
  size_t base = (size_t)bt*CHW + p2*2;
  float s0=0.f,s1=0.f,q0=0.f,q1=0.f;
  #pragma unroll 8
  for (int c=0;c<Cc;c++){
    float2 r = *(const float2*)&g_z_r[base + (size_t)c*HW];
    float2 im = *(const float2*)&g_z_i[base + (size_t)c*HW];
    s0 += r.x + im.x; s1 += r.y + im.y;
    q0 += r.x*r.x + im.x*im.x; q1 += r.y*r.y + im.y*im.y;
  }
  float m0 = s0*(1.f/64.f), m1 = s1*(1.f/64.f);
  float i0 = rsqrtf(q0*(1.f/64.f) - m0*m0 + 1e-5f);
  float i1 = rsqrtf(q1*(1.f/64.f) - m1*m1 + 1e-5f);
  int lane = threadIdx.x & 31, wid = threadIdx.x >> 5;
  for (int c=0;c<Cc;c++){
    float2 r = *(const float2*)&g_z_r[base + (size_t)c*HW];
    float2 im = *(const float2*)&g_z_i[base + (size_t)c*HW];
    float gr = lg[c], br = lb[c], gi = lg[c+32], bi = lb[c+32];
    float nr0 = (r.x-m0)*i0*gr+br, nr1 = (r.y-m1)*i1*gr+br;
    float ni0 = (im.x-m0)*i0*gi+bi, ni1 = (im.y-m1)*i1*gi+bi;
    *(float2*)&g_znc_r[base + (size_t)c*HW] = make_float2(nr0, nr1);
    *(float2*)&g_znc_i[base + (size_t)c*HW] = make_float2(ni0, ni1);
    float mag = sqrtf(nr0*nr0 + ni0*ni0) + sqrtf(nr1*nr1 + ni1*ni1);
    #pragma unroll
    for (int off=16; off; off>>=1) mag += __shfl_xor_sync(0xffffffffu, mag, off);
    if (lane == 0) cacc2[wid][c] = mag;
  }
  __syncthreads();
  if (threadIdx.x < 32){
    float s = 0.f;
    #pragma unroll
    for (int w=0; w<8; w++) s += cacc2[w][threadIdx.x];
    g_ctxp[blockIdx.x*32 + threadIdx.x] = s;
  }
}

// ---------------- K5: evo + input gain (small) ----------------
__global__ void k_gates(const float* __restrict__ dt, const float* __restrict__ alpha,
                        const float* __restrict__ omega, const float* __restrict__ gW,
                        const float* __restrict__ gb){
  int i = threadIdx.x; if (i >= NBT*Cc) return;
  int bt = i >> 5, c = i & 31;
  float dtv = dt[bt];
  float a = alpha[c];
  float sp = (a > 0.f) ? a + log1pf(expf(-a)) : log1pf(expf(a));
  float er = expf(-dtv*sp);
  float sn, cs; sincosf(dtv*omega[c], &sn, &cs);
  g_evo[i] = make_float2(er*cs, er*sn);
  float acc = gb[c];
  for (int k=0;k<32;k++){
    float ctx = 0.f;
    for (int sb=0; sb<8; sb++) ctx += g_ctxp[(bt*8+sb)*32 + k];
    acc += (ctx * (1.f/4096.f)) * gW[k*32 + c];
  }
  g_gain[i] = 1.f/(1.f + expf(-acc));
}

// ---------------- K6: time scan + threefry noise + residual ----------------
__global__ void k_scan(const float* __restrict__ dt, const float* __restrict__ sigma,
                       uint32_t k1a, uint32_t k1b, uint32_t k2a, uint32_t k2b){
  int gid = blockIdx.x*256 + threadIdx.x;
  int b = gid / (Cc*HW); int rem = gid - b*Cc*HW; int c = rem >> 12; int px = rem & 4095;
  float hr=0.f, hi=0.f;
  float sg = sigma[c];
  for (int t=0;t<Tt;t++){
    int btc = (b*Tt + t)*Cc + c;
    size_t base = (size_t)btc*HW + px;
    float2 e = g_evo[btc];
    float gn = g_gain[btc];
    float ur = g_znc_r[base]*gn, ui = g_znc_i[base]*gn;
    float nhr = e.x*hr - e.y*hi + ur;
    float nhi = e.x*hi + e.y*hr + ui;
    hr = nhr; hi = nhi;
    float sc = sg * sqrtf(dt[b*Tt+t] + 1e-6f);
    float er = tf_normal(k1a, k1b, (uint32_t)base);
    float ei = tf_normal(k2a, k2b, (uint32_t)base);
    g_x2_r[base] = hr + sc*er + g_z_r[base];
    g_x2_i[base] = hi + sc*ei + g_z_i[base];
  }
}

// ---------------- K7: fused MLP on mma.sync tf32 ----------------
// smem: Xs[64][136], Hs[64][136], Wc[64][72], Wc2[64][72]
#define MLP_SMEM_FLOATS (64*136 + 64*136 + 64*72 + 64*72)
__global__ void k_mlp(const float* __restrict__ w1, const float* __restrict__ b1,
                      const float* __restrict__ w2, const float* __restrict__ b2,
                      float* __restrict__ out){
  extern __shared__ float smemf[];
  float* Xs  = smemf;                 // [k][m] pitch 136
  float* Hs  = smemf + 64*136;        // [k2][m] pitch 136
  float* Wc  = smemf + 2*64*136;      // [k][n] pitch 72
  float* Wc2 = smemf + 2*64*136 + 64*72;
  int m0 = blockIdx.x*128;
  int bt = m0 >> 12, px0 = m0 & 4095;
  int tid = threadIdx.x, lane = tid & 31, w = tid >> 5;
  int lm = lane >> 2, lk = lane & 3;
  int mbase = w*16;
  // stage X (tf32-rounded)
  for (int idx=tid; idx<8192; idx+=256){
    int m = idx & 127, k = idx >> 7;
    const float* plane = (k < 32) ? g_x2_r : g_x2_i;
    Xs[k*136 + m] = to_tf32(plane[((size_t)bt*Cc + (k & 31))*HW + px0 + m]);
  }
  float oacc[8][4];
  #pragma unroll
  for (int nt=0;nt<8;nt++)
    #pragma unroll
    for (int j=0;j<4;j++) oacc[nt][j] = 0.f;

  for (int nc=0; nc<4; nc++){
    __syncthreads();   // Xs ready (first iter) / Wc,Wc2,Hs reuse safe
    for (int idx=tid; idx<4096; idx+=256){
      int n = idx & 63, k = idx >> 6;
      Wc[k*72 + n] = to_tf32(w1[(size_t)k*256 + nc*64 + n]);
    }
    for (int idx=tid; idx<4096; idx+=256){
      int n2 = idx & 63, k2 = idx >> 6;
      Wc2[k2*72 + n2] = to_tf32(w2[(size_t)(nc*64 + k2)*64 + n2]);
    }
    __syncthreads();
    // stage A: H = X @ Wc
    float hacc[8][4];
    #pragma unroll
    for (int nt=0;nt<8;nt++)
      #pragma unroll
      for (int j=0;j<4;j++) hacc[nt][j] = 0.f;
    #pragma unroll
    for (int ch=0; ch<8; ch++){
      const float* ap = &Xs[(ch*8 + lk)*136 + mbase + lm];
      uint32_t a0 = __float_as_uint(ap[0]);
      uint32_t a1 = __float_as_uint(ap[8]);
      uint32_t a2 = __float_as_uint(ap[4*136]);
      uint32_t a3 = __float_as_uint(ap[4*136 + 8]);
      const float* bp = &Wc[(ch*8 + lk)*72 + lm];
      #pragma unroll
      for (int nt=0; nt<8; nt++){
        uint32_t b0 = __float_as_uint(bp[nt*8]);
        uint32_t b1 = __float_as_uint(bp[4*72 + nt*8]);
        mma_tf32(hacc[nt], a0, a1, a2, a3, b0, b1);
      }
    }
    // bias + GELU -> Hs[k2][m] (tf32-rounded)
    #pragma unroll
    for (int nt=0; nt<8; nt++){
      int n = nt*8 + 2*lk;
      float bb0 = b1[nc*64 + n], bb1 = b1[nc*64 + n + 1];
      #pragma unroll
      for (int j=0;j<4;j++){
        float v = hacc[nt][j] + ((j & 1) ? bb1 : bb0);
        float gl = 0.5f*v*(1.f + tanhf(0.7978845608028654f*(v + 0.044715f*v*v*v)));
        int nn = n + (j & 1);
        int mm = mbase + lm + ((j >> 1) ? 8 : 0);
        Hs[nn*136 + mm] = to_tf32(gl);
      }
    }
    __syncthreads();
    // stage B: out += H @ Wc2
    #pragma unroll
    for (int ch=0; ch<8; ch++){
      const float* ap = &Hs[(ch*8 + lk)*136 + mbase + lm];
      uint32_t a0 = __float_as_uint(ap[0]);
      uint32_t a1 = __float_as_uint(ap[8]);
      uint32_t a2 = __float_as_uint(ap[4*136]);
      uint32_t a3 = __float_as_uint(ap[4*136 + 8]);
      const float* bp = &Wc2[(ch*8 + lk)*72 + lm];
      #pragma unroll
      for (int nt=0; nt<8; nt++){
        uint32_t b0 = __float_as_uint(bp[nt*8]);
        uint32_t b1 = __float_as_uint(bp[4*72 + nt*8]);
        mma_tf32(oacc[nt], a0, a1, a2, a3, b0, b1);
      }
    }
  }
  // epilogue: + b2 + residual, write out
  #pragma unroll
  for (int nt=0; nt<8; nt++){
    int n = nt*8 + 2*lk;
    float bb0 = b2[n], bb1 = b2[n+1];
    #pragma unroll
    for (int j=0;j<4;j++){
      int nn = n + (j & 1);
      int mm = mbase + lm + ((j >> 1) ? 8 : 0);
      int m = px0 + mm;
      float res = (nn < 32) ? g_x2_r[((size_t)bt*Cc + nn)*HW + m]
                            : g_x2_i[((size_t)bt*Cc + (nn-32))*HW + m];
      out[((size_t)bt*64 + nn)*HW + m] = oacc[nt][j] + ((j & 1) ? bb1 : bb0) + res;
    }
  }
}

// ---------------- host launcher ----------------
extern "C" void kernel_launch(void* const* d_in, const int* in_sizes, int n_in,
                              void* d_out, int out_size){
  const float* x_real = (const float*)d_in[0];
  const float* x_imag = (const float*)d_in[1];
  const float* dt     = (const float*)d_in[2];
  const float* ln_s_g = (const float*)d_in[3];
  const float* ln_s_b = (const float*)d_in[4];
  const float* cliffw = (const float*)d_in[5];
  const float* cliffb = (const float*)d_in[6];
  const float* specwr = (const float*)d_in[7];
  const float* specwi = (const float*)d_in[8];
  const float* gate   = (const float*)d_in[9];
  const float* ln_t_g = (const float*)d_in[10];
  const float* ln_t_b = (const float*)d_in[11];
  const float* alpha  = (const float*)d_in[12];
  const float* omega  = (const float*)d_in[13];
  const float* gain_W = (const float*)d_in[14];
  const float* gain_b = (const float*)d_in[15];
  const float* sigma  = (const float*)d_in[16];
  const float* pw1    = (const float*)d_in[17];
  const float* pb1    = (const float*)d_in[18];
  const float* pw2    = (const float*)d_in[19];
  const float* pb2    = (const float*)d_in[20];
  float* out = (float*)d_out;

  uint32_t k1a,k1b,k2a,k2b;
  tf_block(0u, 42u, 0u, 0u, &k1a, &k1b);   // keys[0]
  tf_block(0u, 42u, 0u, 1u, &k2a, &k2b);   // keys[1]

  static int smem_set = 0;
  if (!smem_set){
    cudaFuncSetAttribute(k_mlp, cudaFuncAttributeMaxDynamicSharedMemorySize,
                         MLP_SMEM_FLOATS*4);
    cudaFuncSetAttribute(k_conv, cudaFuncAttributeMaxDynamicSharedMemorySize,
                         CONV_SMEM_FLOATS*4);
    smem_set = 1;
  }

  k_wprep<<<144, 256>>>(cliffw);
  k_ln_spatial<<<128, 256>>>(x_real, x_imag, ln_s_g, ln_s_b);
  k_conv<<<dim3(32, 16), 256, CONV_SMEM_FLOATS*4>>>(cliffb);
  k_spec<<<512, 256>>>(specwr, specwi, gate, x_real, x_imag);
  k_ln_temporal<<<128, 256>>>(ln_t_g, ln_t_b);
  k_gates<<<1, 512>>>(dt, alpha, omega, gain_W, gain_b);
  k_scan<<<1024, 256>>>(dt, sigma, k1a, k1b, k2a, k2b);
  k_mlp<<<512, 256, MLP_SMEM_FLOATS*4>>>(pw1, pb1, pw2, pb2, out);
}